// round 1
// baseline (speedup 1.0000x reference)
#include <cuda_runtime.h>
#include <cuda_bf16.h>
#include <cstddef>

#define N_NODES 50000
#define N_EDGES 800000
#define FIN     256
#define NHID    64

// ---------------- device scratch (static, allocation-free) ----------------
__device__ float g_xw  [3 * N_NODES * NHID];   // x @ W1 per view
__device__ float g_acc [3 * N_NODES * NHID];   // layer-1 aggregation buffer
__device__ float g_dinv1[3 * N_NODES];         // deg^-1/2 (weighted, layer 1)
__device__ float g_dinv2[3 * N_NODES];         // deg^-1/2 (ones, layer 2)
__device__ float g_hw  [3 * N_NODES];          // h @ W2 per view
__device__ float g_coef1[3 * N_EDGES];         // per-edge norm, layer 1
__device__ float g_coef2[3 * N_EDGES];         // per-edge norm, layer 2

// ---------------- degree init: self-loop weight 1 ----------------
__global__ void k_init_deg() {
    int i = blockIdx.x * blockDim.x + threadIdx.x;
    if (i < 3 * N_NODES) { g_dinv1[i] = 1.0f; g_dinv2[i] = 1.0f; }
}

// ---------------- degree accumulation ----------------
__global__ void k_deg(const int* __restrict__ ei0, const int* __restrict__ ei1,
                      const int* __restrict__ ei2,
                      const float* __restrict__ w0, const float* __restrict__ w1,
                      const float* __restrict__ w2) {
    int v = blockIdx.y;
    const int*   ei = (v == 0) ? ei0 : (v == 1) ? ei1 : ei2;
    const float* w  = (v == 0) ? w0  : (v == 1) ? w1  : w2;
    int e = blockIdx.x * blockDim.x + threadIdx.x;
    if (e >= N_EDGES) return;
    int d = ei[N_EDGES + e];
    atomicAdd(&g_dinv1[v * N_NODES + d], w[e]);
    atomicAdd(&g_dinv2[v * N_NODES + d], 1.0f);
}

// ---------------- deg -> deg^-1/2 (deg >= 1 always: self loop) ----------------
__global__ void k_rsqrt() {
    int i = blockIdx.x * blockDim.x + threadIdx.x;
    if (i < 3 * N_NODES) {
        g_dinv1[i] = rsqrtf(g_dinv1[i]);
        g_dinv2[i] = rsqrtf(g_dinv2[i]);
    }
}

// ---------------- per-edge normalization coefficients ----------------
__global__ void k_coef(const int* __restrict__ ei0, const int* __restrict__ ei1,
                       const int* __restrict__ ei2,
                       const float* __restrict__ w0, const float* __restrict__ w1,
                       const float* __restrict__ w2) {
    int v = blockIdx.y;
    const int*   ei = (v == 0) ? ei0 : (v == 1) ? ei1 : ei2;
    const float* w  = (v == 0) ? w0  : (v == 1) ? w1  : w2;
    int e = blockIdx.x * blockDim.x + threadIdx.x;
    if (e >= N_EDGES) return;
    int s = ei[e], d = ei[N_EDGES + e];
    const float* d1 = g_dinv1 + v * N_NODES;
    const float* d2 = g_dinv2 + v * N_NODES;
    g_coef1[v * N_EDGES + e] = d1[s] * w[e] * d1[d];
    g_coef2[v * N_EDGES + e] = d2[s] * d2[d];
}

// ---------------- SGEMM: xw = x @ W1_v ; acc = xw * dinv1^2 (self loop) -----
// M=50000, N=64 per view, K=256. Tile 128x64x32, 256 threads, 8x4 per thread.
#define GM 128
#define GN 64
#define GK 32

__global__ __launch_bounds__(256) void k_gemm(const float* __restrict__ x,
                                              const float* __restrict__ Wa,
                                              const float* __restrict__ Wb,
                                              const float* __restrict__ Wc) {
    int v = blockIdx.y;
    const float* W = (v == 0) ? Wa : (v == 1) ? Wb : Wc;

    __shared__ float As[GK][GM + 4];   // +4 pad: conflict-free + 16B-aligned rows
    __shared__ float Bs[GK][GN];

    int tid = threadIdx.x;
    int rowBlock = blockIdx.x * GM;
    int tr = tid >> 4;     // 0..15 -> rows tr*8..tr*8+7
    int tc = tid & 15;     // 0..15 -> cols tc*4..tc*4+3

    float acc[8][4];
#pragma unroll
    for (int r = 0; r < 8; r++)
#pragma unroll
        for (int c = 0; c < 4; c++) acc[r][c] = 0.0f;

    for (int k0 = 0; k0 < FIN; k0 += GK) {
        // load A tile (128x32) as float4, store transposed
#pragma unroll
        for (int i = 0; i < 4; i++) {
            int idx = tid + i * 256;       // float4 index in tile (128*8)
            int r = idx >> 3, c4 = idx & 7;
            int grow = rowBlock + r;
            float4 a = (grow < N_NODES)
                ? *(const float4*)(x + (size_t)grow * FIN + k0 + c4 * 4)
                : make_float4(0.f, 0.f, 0.f, 0.f);
            As[c4 * 4 + 0][r] = a.x;
            As[c4 * 4 + 1][r] = a.y;
            As[c4 * 4 + 2][r] = a.z;
            As[c4 * 4 + 3][r] = a.w;
        }
        // load B tile (32x64) as float4
#pragma unroll
        for (int i = 0; i < 2; i++) {
            int idx = tid + i * 256;       // float4 index (32*16)
            int r = idx >> 4, c4 = idx & 15;
            *(float4*)&Bs[r][c4 * 4] =
                *(const float4*)(W + (size_t)(k0 + r) * NHID + c4 * 4);
        }
        __syncthreads();

#pragma unroll
        for (int kk = 0; kk < GK; kk++) {
            float4 b  = *(float4*)&Bs[kk][tc * 4];
            float4 a0 = *(float4*)&As[kk][tr * 8];
            float4 a1 = *(float4*)&As[kk][tr * 8 + 4];
            float a[8] = {a0.x, a0.y, a0.z, a0.w, a1.x, a1.y, a1.z, a1.w};
#pragma unroll
            for (int r = 0; r < 8; r++) {
                acc[r][0] = fmaf(a[r], b.x, acc[r][0]);
                acc[r][1] = fmaf(a[r], b.y, acc[r][1]);
                acc[r][2] = fmaf(a[r], b.z, acc[r][2]);
                acc[r][3] = fmaf(a[r], b.w, acc[r][3]);
            }
        }
        __syncthreads();
    }

    float* xw  = g_xw  + (size_t)v * N_NODES * NHID;
    float* agg = g_acc + (size_t)v * N_NODES * NHID;
#pragma unroll
    for (int r = 0; r < 8; r++) {
        int grow = rowBlock + tr * 8 + r;
        if (grow < N_NODES) {
            float d = g_dinv1[v * N_NODES + grow];
            float s = d * d;
            float4 o = make_float4(acc[r][0], acc[r][1], acc[r][2], acc[r][3]);
            *(float4*)(xw  + (size_t)grow * NHID + tc * 4) = o;
            *(float4*)(agg + (size_t)grow * NHID + tc * 4) =
                make_float4(o.x * s, o.y * s, o.z * s, o.w * s);
        }
    }
}

// ---------------- layer-1 scatter: acc[dst] += xw[src] * coef --------------
// 16 lanes per edge, one float4 atomic per lane.
__global__ void k_scatter1(const int* __restrict__ ei0, const int* __restrict__ ei1,
                           const int* __restrict__ ei2) {
    int v = blockIdx.y;
    const int* ei = (v == 0) ? ei0 : (v == 1) ? ei1 : ei2;
    int idx = blockIdx.x * blockDim.x + threadIdx.x;
    int e = idx >> 4;
    int c = idx & 15;
    if (e >= N_EDGES) return;
    int s = ei[e], d = ei[N_EDGES + e];
    float coef = g_coef1[v * N_EDGES + e];
    float4 m = *((const float4*)(g_xw + ((size_t)v * N_NODES + s) * NHID) + c);
    float4* dp = (float4*)(g_acc + ((size_t)v * N_NODES + d) * NHID) + c;
    atomicAdd(dp, make_float4(m.x * coef, m.y * coef, m.z * coef, m.w * coef));
}

// ---------------- epilogue: relu+bias, feature sum, h@W2, x_flat init ------
// one warp per node
__global__ void k_epilogue(float* __restrict__ out,
                           const float* __restrict__ b1a, const float* __restrict__ b1b,
                           const float* __restrict__ b1c,
                           const float* __restrict__ W2a, const float* __restrict__ W2b,
                           const float* __restrict__ W2c,
                           const float* __restrict__ b2a, const float* __restrict__ b2b,
                           const float* __restrict__ b2c) {
    int gtid = blockIdx.x * blockDim.x + threadIdx.x;
    int node = gtid >> 5;
    int lane = gtid & 31;
    if (node >= N_NODES) return;

    float2 fsum = make_float2(0.f, 0.f);
    float selfsum = 0.f;
#pragma unroll
    for (int v = 0; v < 3; v++) {
        const float* b1 = (v == 0) ? b1a : (v == 1) ? b1b : b1c;
        const float* W2 = (v == 0) ? W2a : (v == 1) ? W2b : W2c;
        float2 a = *(const float2*)(g_acc + ((size_t)v * N_NODES + node) * NHID + lane * 2);
        float h0 = fmaxf(a.x + b1[lane * 2 + 0], 0.f);
        float h1 = fmaxf(a.y + b1[lane * 2 + 1], 0.f);
        fsum.x += h0;
        fsum.y += h1;
        float p = h0 * W2[lane * 2 + 0] + h1 * W2[lane * 2 + 1];
#pragma unroll
        for (int o = 16; o > 0; o >>= 1) p += __shfl_xor_sync(0xffffffffu, p, o);
        if (lane == 0) g_hw[v * N_NODES + node] = p;
        float d2 = g_dinv2[v * N_NODES + node];
        selfsum = fmaf(p, d2 * d2, selfsum);
    }
    // features = f1+f2+f3
    *(float2*)(out + N_NODES + (size_t)node * NHID + lane * 2) = fsum;
    // x_flat init: layer-2 self-loop terms + all b2
    if (lane == 0) out[node] = selfsum + b2a[0] + b2b[0] + b2c[0];
}

// ---------------- layer-2 scatter: out[dst] += hw[src] * coef2 -------------
__global__ void k_scatter2(float* __restrict__ out,
                           const int* __restrict__ ei0, const int* __restrict__ ei1,
                           const int* __restrict__ ei2) {
    int v = blockIdx.y;
    const int* ei = (v == 0) ? ei0 : (v == 1) ? ei1 : ei2;
    int e = blockIdx.x * blockDim.x + threadIdx.x;
    if (e >= N_EDGES) return;
    int s = ei[e], d = ei[N_EDGES + e];
    atomicAdd(out + d, g_hw[v * N_NODES + s] * g_coef2[v * N_EDGES + e]);
}

// ---------------- launch ----------------
extern "C" void kernel_launch(void* const* d_in, const int* in_sizes, int n_in,
                              void* d_out, int out_size) {
    const float* x   = (const float*)d_in[0];
    const int*   ei0 = (const int*)d_in[1];
    const int*   ei1 = (const int*)d_in[2];
    const int*   ei2 = (const int*)d_in[3];
    const float* w0  = (const float*)d_in[4];
    const float* w1  = (const float*)d_in[5];
    const float* w2  = (const float*)d_in[6];
    const float* W1a = (const float*)d_in[7];
    const float* b1a = (const float*)d_in[8];
    const float* W2a = (const float*)d_in[9];
    const float* b2a = (const float*)d_in[10];
    const float* W1b = (const float*)d_in[11];
    const float* b1b = (const float*)d_in[12];
    const float* W2b = (const float*)d_in[13];
    const float* b2b = (const float*)d_in[14];
    const float* W1c = (const float*)d_in[15];
    const float* b1c = (const float*)d_in[16];
    const float* W2c = (const float*)d_in[17];
    const float* b2c = (const float*)d_in[18];
    float* out = (float*)d_out;

    k_init_deg<<<(3 * N_NODES + 255) / 256, 256>>>();
    k_deg<<<dim3((N_EDGES + 255) / 256, 3), 256>>>(ei0, ei1, ei2, w0, w1, w2);
    k_rsqrt<<<(3 * N_NODES + 255) / 256, 256>>>();
    k_coef<<<dim3((N_EDGES + 255) / 256, 3), 256>>>(ei0, ei1, ei2, w0, w1, w2);
    k_gemm<<<dim3((N_NODES + GM - 1) / GM, 3), 256>>>(x, W1a, W1b, W1c);
    k_scatter1<<<dim3((N_EDGES * 16 + 255) / 256, 3), 256>>>(ei0, ei1, ei2);
    k_epilogue<<<(N_NODES * 32 + 255) / 256, 256>>>(out, b1a, b1b, b1c,
                                                    W2a, W2b, W2c, b2a, b2b, b2c);
    k_scatter2<<<dim3((N_EDGES + 255) / 256, 3), 256>>>(out, ei0, ei1, ei2);
}

// round 3
// speedup vs baseline: 1.1487x; 1.1487x over previous
#include <cuda_runtime.h>
#include <cstdint>
#include <cstddef>

#define N_NODES 50000
#define N_EDGES 800000
#define FIN     256
#define NHID    64
#define NV      (3 * N_NODES)          // 150000 node-view pairs
#define NBLK    ((NV + 255) / 256)     // 586 scan blocks

// ---------------- device scratch (static, allocation-free) ----------------
__device__ float g_xw  [3 * N_NODES * NHID];   // x @ W1 per view
__device__ float g_degW[NV];                    // weighted degree (incl self 1.0)
__device__ int   g_degI[NV];                    // integer in-degree (excl self)
__device__ float g_dinv[NV * 2];                // interleaved (dinv1, dinv2)
__device__ float g_hw  [NV];                    // h @ W2 per node-view
__device__ int   g_off [NV];                    // CSR offsets
__device__ int   g_cur [NV];                    // fill cursors
__device__ int2  g_e1  [3 * N_EDGES];           // {src, coef1-bits}
__device__ int2  g_e2  [3 * N_EDGES];           // {src, coef2-bits}
__device__ int   g_bsum[1024];                  // scan block sums

// ---------------- init: degW=1 (self loop), degI=0 ----------------
__global__ void k_zero() {
    int i = blockIdx.x * blockDim.x + threadIdx.x;
    if (i < NV) { g_degW[i] = 1.0f; g_degI[i] = 0; }
}

// ---------------- degree accumulation ----------------
__global__ void k_deg(const int* __restrict__ ei0, const int* __restrict__ ei1,
                      const int* __restrict__ ei2,
                      const float* __restrict__ w0, const float* __restrict__ w1,
                      const float* __restrict__ w2) {
    int v = blockIdx.y;
    const int*   ei = (v == 0) ? ei0 : (v == 1) ? ei1 : ei2;
    const float* w  = (v == 0) ? w0  : (v == 1) ? w1  : w2;
    int e = blockIdx.x * blockDim.x + threadIdx.x;
    if (e >= N_EDGES) return;
    int nv = v * N_NODES + ei[N_EDGES + e];
    atomicAdd(&g_degW[nv], w[e]);
    atomicAdd(&g_degI[nv], 1);
}

// ---------------- scan stage 1: per-block sums of degI ----------------
__global__ void k_scan1() {
    __shared__ int s[256];
    int t = threadIdx.x;
    int i = blockIdx.x * 256 + t;
    s[t] = (i < NV) ? g_degI[i] : 0;
    __syncthreads();
#pragma unroll
    for (int o = 128; o > 0; o >>= 1) {
        if (t < o) s[t] += s[t + o];
        __syncthreads();
    }
    if (t == 0) g_bsum[blockIdx.x] = s[0];
}

// ---------------- scan stage 2: exclusive scan of block sums (1 block) ----
__global__ void k_scan2() {
    __shared__ int s[1024];
    int t = threadIdx.x;
    int v = (t < NBLK) ? g_bsum[t] : 0;
    s[t] = v;
    __syncthreads();
#pragma unroll
    for (int o = 1; o < 1024; o <<= 1) {
        int x = (t >= o) ? s[t - o] : 0;
        __syncthreads();
        s[t] += x;
        __syncthreads();
    }
    if (t < NBLK) g_bsum[t] = s[t] - v;   // exclusive
}

// ---------------- scan stage 3: offsets + cursors + dinv ----------------
__global__ void k_scan3() {
    __shared__ int s[256];
    int t = threadIdx.x;
    int i = blockIdx.x * 256 + t;
    int v = (i < NV) ? g_degI[i] : 0;
    s[t] = v;
    __syncthreads();
#pragma unroll
    for (int o = 1; o < 256; o <<= 1) {
        int x = (t >= o) ? s[t - o] : 0;
        __syncthreads();
        s[t] += x;
        __syncthreads();
    }
    if (i < NV) {
        int off = g_bsum[blockIdx.x] + s[t] - v;
        g_off[i] = off;
        g_cur[i] = off;
        g_dinv[2 * i + 0] = rsqrtf(g_degW[i]);
        g_dinv[2 * i + 1] = rsqrtf((float)(g_degI[i] + 1));
    }
}

// ---------------- CSR fill: coefs + packed edge records ----------------
__global__ void k_fill(const int* __restrict__ ei0, const int* __restrict__ ei1,
                       const int* __restrict__ ei2,
                       const float* __restrict__ w0, const float* __restrict__ w1,
                       const float* __restrict__ w2) {
    int v = blockIdx.y;
    const int*   ei = (v == 0) ? ei0 : (v == 1) ? ei1 : ei2;
    const float* w  = (v == 0) ? w0  : (v == 1) ? w1  : w2;
    int e = blockIdx.x * blockDim.x + threadIdx.x;
    if (e >= N_EDGES) return;
    int s = ei[e], d = ei[N_EDGES + e];
    int nv = v * N_NODES + d;
    const float2* dv = (const float2*)g_dinv;
    float2 ds = dv[v * N_NODES + s];
    float2 dd = dv[nv];
    float c1 = ds.x * w[e] * dd.x;
    float c2 = ds.y * dd.y;
    int slot = atomicAdd(&g_cur[nv], 1);
    g_e1[slot] = make_int2(s, __float_as_int(c1));
    g_e2[slot] = make_int2(s, __float_as_int(c2));
}

// ---------------- SGEMM: xw = x @ W1_v (proven round-1 version) ----------
#define GM 128
#define GK 32

__global__ __launch_bounds__(256) void k_gemm(const float* __restrict__ x,
                                              const float* __restrict__ Wa,
                                              const float* __restrict__ Wb,
                                              const float* __restrict__ Wc) {
    int v = blockIdx.y;
    const float* W = (v == 0) ? Wa : (v == 1) ? Wb : Wc;

    __shared__ float As[GK][GM + 4];
    __shared__ float Bs[GK][NHID];

    int tid = threadIdx.x;
    int rowBlock = blockIdx.x * GM;
    int tr = tid >> 4;
    int tc = tid & 15;

    float acc[8][4];
#pragma unroll
    for (int r = 0; r < 8; r++)
#pragma unroll
        for (int c = 0; c < 4; c++) acc[r][c] = 0.0f;

    for (int k0 = 0; k0 < FIN; k0 += GK) {
#pragma unroll
        for (int i = 0; i < 4; i++) {
            int idx = tid + i * 256;
            int r = idx >> 3, c4 = idx & 7;
            int grow = rowBlock + r;
            float4 a = (grow < N_NODES)
                ? *(const float4*)(x + (size_t)grow * FIN + k0 + c4 * 4)
                : make_float4(0.f, 0.f, 0.f, 0.f);
            As[c4 * 4 + 0][r] = a.x;
            As[c4 * 4 + 1][r] = a.y;
            As[c4 * 4 + 2][r] = a.z;
            As[c4 * 4 + 3][r] = a.w;
        }
#pragma unroll
        for (int i = 0; i < 2; i++) {
            int idx = tid + i * 256;
            int r = idx >> 4, c4 = idx & 15;
            *(float4*)&Bs[r][c4 * 4] =
                *(const float4*)(W + (size_t)(k0 + r) * NHID + c4 * 4);
        }
        __syncthreads();

#pragma unroll
        for (int kk = 0; kk < GK; kk++) {
            float4 b  = *(float4*)&Bs[kk][tc * 4];
            float4 a0 = *(float4*)&As[kk][tr * 8];
            float4 a1 = *(float4*)&As[kk][tr * 8 + 4];
            float a[8] = {a0.x, a0.y, a0.z, a0.w, a1.x, a1.y, a1.z, a1.w};
#pragma unroll
            for (int r = 0; r < 8; r++) {
                acc[r][0] = fmaf(a[r], b.x, acc[r][0]);
                acc[r][1] = fmaf(a[r], b.y, acc[r][1]);
                acc[r][2] = fmaf(a[r], b.z, acc[r][2]);
                acc[r][3] = fmaf(a[r], b.w, acc[r][3]);
            }
        }
        __syncthreads();
    }

    float* xw = g_xw + (size_t)v * N_NODES * NHID;
#pragma unroll
    for (int r = 0; r < 8; r++) {
        int grow = rowBlock + tr * 8 + r;
        if (grow < N_NODES) {
            *(float4*)(xw + (size_t)grow * NHID + tc * 4) =
                make_float4(acc[r][0], acc[r][1], acc[r][2], acc[r][3]);
        }
    }
}

// ---------------- gather1: layer-1 agg + bias/relu + featsum + h@W2 -------
// one warp per node; lanes own 2 of the 64 hidden dims.
__global__ void k_gather1(float* __restrict__ out,
                          const float* __restrict__ b1a, const float* __restrict__ b1b,
                          const float* __restrict__ b1c,
                          const float* __restrict__ W2a, const float* __restrict__ W2b,
                          const float* __restrict__ W2c,
                          const float* __restrict__ b2a, const float* __restrict__ b2b,
                          const float* __restrict__ b2c) {
    int gtid = blockIdx.x * blockDim.x + threadIdx.x;
    int node = gtid >> 5;
    int lane = gtid & 31;
    if (node >= N_NODES) return;

    float2 fsum = make_float2(0.f, 0.f);
    float selfsum = 0.f;
#pragma unroll
    for (int v = 0; v < 3; v++) {
        const float* b1 = (v == 0) ? b1a : (v == 1) ? b1b : b1c;
        const float* W2 = (v == 0) ? W2a : (v == 1) ? W2b : W2c;
        int nv = v * N_NODES + node;
        const float2* xwv = (const float2*)g_xw + (size_t)v * N_NODES * 32;

        float d1 = g_dinv[2 * nv + 0];
        float d2 = g_dinv[2 * nv + 1];
        float2 self = xwv[(size_t)node * 32 + lane];
        float sc = d1 * d1;
        float2 acc = make_float2(self.x * sc, self.y * sc);

        int base = g_off[nv];
        int cnt  = g_degI[nv];
        for (int e = 0; e < cnt; e++) {
            int2 p = g_e1[base + e];              // broadcast load
            float c = __int_as_float(p.y);
            float2 m = xwv[(size_t)p.x * 32 + lane];
            acc.x = fmaf(m.x, c, acc.x);
            acc.y = fmaf(m.y, c, acc.y);
        }

        float h0 = fmaxf(acc.x + b1[lane * 2 + 0], 0.f);
        float h1 = fmaxf(acc.y + b1[lane * 2 + 1], 0.f);
        fsum.x += h0;
        fsum.y += h1;
        float p = h0 * W2[lane * 2 + 0] + h1 * W2[lane * 2 + 1];
#pragma unroll
        for (int o = 16; o > 0; o >>= 1) p += __shfl_xor_sync(0xffffffffu, p, o);
        if (lane == 0) g_hw[nv] = p;
        selfsum = fmaf(p, d2 * d2, selfsum);
    }
    *(float2*)(out + N_NODES + (size_t)node * NHID + lane * 2) = fsum;
    if (lane == 0) out[node] = selfsum + b2a[0] + b2b[0] + b2c[0];
}

// ---------------- gather2: out[node] += sum hw[src]*c2 over views ---------
// one warp per node, lanes stride edges.
__global__ void k_gather2(float* __restrict__ out) {
    int gtid = blockIdx.x * blockDim.x + threadIdx.x;
    int node = gtid >> 5;
    int lane = gtid & 31;
    if (node >= N_NODES) return;

    float add = 0.f;
#pragma unroll
    for (int v = 0; v < 3; v++) {
        int nv = v * N_NODES + node;
        int base = g_off[nv];
        int cnt  = g_degI[nv];
        const float* hwv = g_hw + v * N_NODES;
        for (int e = lane; e < cnt; e += 32) {
            int2 p = g_e2[base + e];
            add = fmaf(hwv[p.x], __int_as_float(p.y), add);
        }
    }
#pragma unroll
    for (int o = 16; o > 0; o >>= 1) add += __shfl_xor_sync(0xffffffffu, add, o);
    if (lane == 0) out[node] += add;
}

// ---------------- launch ----------------
extern "C" void kernel_launch(void* const* d_in, const int* in_sizes, int n_in,
                              void* d_out, int out_size) {
    const float* x   = (const float*)d_in[0];
    const int*   ei0 = (const int*)d_in[1];
    const int*   ei1 = (const int*)d_in[2];
    const int*   ei2 = (const int*)d_in[3];
    const float* w0  = (const float*)d_in[4];
    const float* w1  = (const float*)d_in[5];
    const float* w2  = (const float*)d_in[6];
    const float* W1a = (const float*)d_in[7];
    const float* b1a = (const float*)d_in[8];
    const float* W2a = (const float*)d_in[9];
    const float* b2a = (const float*)d_in[10];
    const float* W1b = (const float*)d_in[11];
    const float* b1b = (const float*)d_in[12];
    const float* W2b = (const float*)d_in[13];
    const float* b2b = (const float*)d_in[14];
    const float* W1c = (const float*)d_in[15];
    const float* b1c = (const float*)d_in[16];
    const float* W2c = (const float*)d_in[17];
    const float* b2c = (const float*)d_in[18];
    float* out = (float*)d_out;

    k_zero<<<NBLK, 256>>>();
    k_deg<<<dim3((N_EDGES + 255) / 256, 3), 256>>>(ei0, ei1, ei2, w0, w1, w2);
    k_scan1<<<NBLK, 256>>>();
    k_scan2<<<1, 1024>>>();
    k_scan3<<<NBLK, 256>>>();
    k_fill<<<dim3((N_EDGES + 255) / 256, 3), 256>>>(ei0, ei1, ei2, w0, w1, w2);
    k_gemm<<<dim3((N_NODES + GM - 1) / GM, 3), 256>>>(x, W1a, W1b, W1c);
    k_gather1<<<(N_NODES * 32 + 255) / 256, 256>>>(out, b1a, b1b, b1c,
                                                   W2a, W2b, W2c, b2a, b2b, b2c);
    k_gather2<<<(N_NODES * 32 + 255) / 256, 256>>>(out);
}

// round 4
// speedup vs baseline: 1.1782x; 1.0257x over previous
#include <cuda_runtime.h>
#include <cuda_bf16.h>
#include <cstdint>
#include <cstddef>

#define N_NODES 50000
#define N_EDGES 800000
#define FIN     256
#define NHID    64
#define NV      (3 * N_NODES)
#define NBLK    ((NV + 255) / 256)

// ---------------- device scratch (static, allocation-free) ----------------
__device__ float g_xw  [3 * N_NODES * NHID];
__device__ float g_degW[NV];
__device__ int   g_degI[NV];
__device__ float g_dinv[NV * 2];
__device__ float g_hw  [NV];
__device__ int   g_off [NV];
__device__ int   g_cur [NV];
__device__ int4  g_ed  [3 * N_EDGES];            // {src, c1-bits, c2-bits, 0}
__device__ int   g_bsum[1024];
__device__ __nv_bfloat16 g_xhi[(size_t)N_NODES * FIN];
__device__ __nv_bfloat16 g_xlo[(size_t)N_NODES * FIN];
__device__ __nv_bfloat16 g_whi[192 * FIN];       // [n_global][k]
__device__ __nv_bfloat16 g_wlo[192 * FIN];

// ---------------- init ----------------
__global__ void k_zero() {
    int i = blockIdx.x * blockDim.x + threadIdx.x;
    if (i < NV) { g_degW[i] = 1.0f; g_degI[i] = 0; }
}

// ---------------- x -> bf16 hi/lo split ----------------
__global__ void k_prepX(const float* __restrict__ x) {
    int i = blockIdx.x * blockDim.x + threadIdx.x;   // per float4
    if (i >= N_NODES * FIN / 4) return;
    float4 a = ((const float4*)x)[i];
    __nv_bfloat16 h0 = __float2bfloat16_rn(a.x);
    __nv_bfloat16 h1 = __float2bfloat16_rn(a.y);
    __nv_bfloat16 h2 = __float2bfloat16_rn(a.z);
    __nv_bfloat16 h3 = __float2bfloat16_rn(a.w);
    __nv_bfloat16 l0 = __float2bfloat16_rn(a.x - __bfloat162float(h0));
    __nv_bfloat16 l1 = __float2bfloat16_rn(a.y - __bfloat162float(h1));
    __nv_bfloat16 l2 = __float2bfloat16_rn(a.z - __bfloat162float(h2));
    __nv_bfloat16 l3 = __float2bfloat16_rn(a.w - __bfloat162float(h3));
    ((ushort4*)g_xhi)[i] = make_ushort4(__bfloat16_as_ushort(h0), __bfloat16_as_ushort(h1),
                                        __bfloat16_as_ushort(h2), __bfloat16_as_ushort(h3));
    ((ushort4*)g_xlo)[i] = make_ushort4(__bfloat16_as_ushort(l0), __bfloat16_as_ushort(l1),
                                        __bfloat16_as_ushort(l2), __bfloat16_as_ushort(l3));
}

// ---------------- W -> transposed bf16 hi/lo ----------------
__global__ void k_prepW(const float* __restrict__ Wa, const float* __restrict__ Wb,
                        const float* __restrict__ Wc) {
    int idx = blockIdx.x * blockDim.x + threadIdx.x;  // over 192*256
    if (idx >= 192 * FIN) return;
    int ng = idx >> 8;         // 0..191
    int k  = idx & 255;
    int v  = ng >> 6;
    int n  = ng & 63;
    const float* W = (v == 0) ? Wa : (v == 1) ? Wb : Wc;
    float f = W[k * NHID + n];
    __nv_bfloat16 h = __float2bfloat16_rn(f);
    __nv_bfloat16 l = __float2bfloat16_rn(f - __bfloat162float(h));
    g_whi[idx] = h;
    g_wlo[idx] = l;
}

// ---------------- degree accumulation ----------------
__global__ void k_deg(const int* __restrict__ ei0, const int* __restrict__ ei1,
                      const int* __restrict__ ei2,
                      const float* __restrict__ w0, const float* __restrict__ w1,
                      const float* __restrict__ w2) {
    int v = blockIdx.y;
    const int*   ei = (v == 0) ? ei0 : (v == 1) ? ei1 : ei2;
    const float* w  = (v == 0) ? w0  : (v == 1) ? w1  : w2;
    int e = blockIdx.x * blockDim.x + threadIdx.x;
    if (e >= N_EDGES) return;
    int nv = v * N_NODES + ei[N_EDGES + e];
    atomicAdd(&g_degW[nv], w[e]);
    atomicAdd(&g_degI[nv], 1);
}

// ---------------- scans ----------------
__global__ void k_scan1() {
    __shared__ int s[256];
    int t = threadIdx.x;
    int i = blockIdx.x * 256 + t;
    s[t] = (i < NV) ? g_degI[i] : 0;
    __syncthreads();
#pragma unroll
    for (int o = 128; o > 0; o >>= 1) {
        if (t < o) s[t] += s[t + o];
        __syncthreads();
    }
    if (t == 0) g_bsum[blockIdx.x] = s[0];
}

__global__ void k_scan2() {
    __shared__ int s[1024];
    int t = threadIdx.x;
    int v = (t < NBLK) ? g_bsum[t] : 0;
    s[t] = v;
    __syncthreads();
#pragma unroll
    for (int o = 1; o < 1024; o <<= 1) {
        int x = (t >= o) ? s[t - o] : 0;
        __syncthreads();
        s[t] += x;
        __syncthreads();
    }
    if (t < NBLK) g_bsum[t] = s[t] - v;
}

__global__ void k_scan3() {
    __shared__ int s[256];
    int t = threadIdx.x;
    int i = blockIdx.x * 256 + t;
    int v = (i < NV) ? g_degI[i] : 0;
    s[t] = v;
    __syncthreads();
#pragma unroll
    for (int o = 1; o < 256; o <<= 1) {
        int x = (t >= o) ? s[t - o] : 0;
        __syncthreads();
        s[t] += x;
        __syncthreads();
    }
    if (i < NV) {
        int off = g_bsum[blockIdx.x] + s[t] - v;
        g_off[i] = off;
        g_cur[i] = off;
        g_dinv[2 * i + 0] = rsqrtf(g_degW[i]);
        g_dinv[2 * i + 1] = rsqrtf((float)(g_degI[i] + 1));
    }
}

// ---------------- CSR fill ----------------
__global__ void k_fill(const int* __restrict__ ei0, const int* __restrict__ ei1,
                       const int* __restrict__ ei2,
                       const float* __restrict__ w0, const float* __restrict__ w1,
                       const float* __restrict__ w2) {
    int v = blockIdx.y;
    const int*   ei = (v == 0) ? ei0 : (v == 1) ? ei1 : ei2;
    const float* w  = (v == 0) ? w0  : (v == 1) ? w1  : w2;
    int e = blockIdx.x * blockDim.x + threadIdx.x;
    if (e >= N_EDGES) return;
    int s = ei[e], d = ei[N_EDGES + e];
    int nv = v * N_NODES + d;
    const float2* dv = (const float2*)g_dinv;
    float2 ds = dv[v * N_NODES + s];
    float2 dd = dv[nv];
    float c1 = ds.x * w[e] * dd.x;
    float c2 = ds.y * dd.y;
    int slot = atomicAdd(&g_cur[nv], 1);
    g_ed[slot] = make_int4(s, __float_as_int(c1), __float_as_int(c2), 0);
}

// ---------------- bf16 mma GEMM: g_xw = x @ [W1a|W1b|W1c] ----------------
// block 256 thr = 8 warps (2 m x 4 n); block tile 128 x 192; warp tile 64 x 48.
__device__ __forceinline__ void mma_bf16(float* d, uint32_t a0, uint32_t a1,
                                         uint32_t a2, uint32_t a3,
                                         uint32_t b0, uint32_t b1) {
    asm volatile("mma.sync.aligned.m16n8k16.row.col.f32.bf16.bf16.f32 "
                 "{%0,%1,%2,%3}, {%4,%5,%6,%7}, {%8,%9}, {%0,%1,%2,%3};"
                 : "+f"(d[0]), "+f"(d[1]), "+f"(d[2]), "+f"(d[3])
                 : "r"(a0), "r"(a1), "r"(a2), "r"(a3), "r"(b0), "r"(b1));
}

__global__ __launch_bounds__(256, 1) void k_gemm_mma() {
    int tid  = threadIdx.x;
    int w    = tid >> 5;
    int lane = tid & 31;
    int g    = lane >> 2;        // groupID
    int tg   = lane & 3;         // threadID in group
    int m0   = blockIdx.x * 128 + (w >> 2) * 64;
    int n0   = (w & 3) * 48;

    float acc[4][6][4];
#pragma unroll
    for (int mf = 0; mf < 4; mf++)
#pragma unroll
        for (int nf = 0; nf < 6; nf++)
#pragma unroll
            for (int j = 0; j < 4; j++) acc[mf][nf][j] = 0.f;

    // precompute clamped row byte-bases (element index into [row*256])
    int rbase[8];
#pragma unroll
    for (int mf = 0; mf < 4; mf++) {
        int r0 = m0 + mf * 16 + g;
        int r1 = r0 + 8;
        rbase[mf * 2 + 0] = min(r0, N_NODES - 1) * FIN;
        rbase[mf * 2 + 1] = min(r1, N_NODES - 1) * FIN;
    }

#pragma unroll 1
    for (int kc = 0; kc < 16; kc++) {
        int k0 = kc * 16;
        int ka = k0 + tg * 2;

        uint32_t ah[4][4], al[4][4];
#pragma unroll
        for (int mf = 0; mf < 4; mf++) {
            const uint32_t* h0 = (const uint32_t*)(g_xhi + rbase[mf * 2 + 0] + ka);
            const uint32_t* h1 = (const uint32_t*)(g_xhi + rbase[mf * 2 + 1] + ka);
            const uint32_t* l0 = (const uint32_t*)(g_xlo + rbase[mf * 2 + 0] + ka);
            const uint32_t* l1 = (const uint32_t*)(g_xlo + rbase[mf * 2 + 1] + ka);
            ah[mf][0] = h0[0]; ah[mf][1] = h1[0]; ah[mf][2] = h0[4]; ah[mf][3] = h1[4];
            al[mf][0] = l0[0]; al[mf][1] = l1[0]; al[mf][2] = l0[4]; al[mf][3] = l1[4];
        }
        uint32_t bh[6][2], bl[6][2];
#pragma unroll
        for (int nf = 0; nf < 6; nf++) {
            int ng = n0 + nf * 8 + g;
            const uint32_t* bhp = (const uint32_t*)(g_whi + ng * FIN + ka);
            const uint32_t* blp = (const uint32_t*)(g_wlo + ng * FIN + ka);
            bh[nf][0] = bhp[0]; bh[nf][1] = bhp[4];
            bl[nf][0] = blp[0]; bl[nf][1] = blp[4];
        }
#pragma unroll
        for (int mf = 0; mf < 4; mf++)
#pragma unroll
            for (int nf = 0; nf < 6; nf++) {
                mma_bf16(acc[mf][nf], ah[mf][0], ah[mf][1], ah[mf][2], ah[mf][3],
                         bh[nf][0], bh[nf][1]);
                mma_bf16(acc[mf][nf], ah[mf][0], ah[mf][1], ah[mf][2], ah[mf][3],
                         bl[nf][0], bl[nf][1]);
                mma_bf16(acc[mf][nf], al[mf][0], al[mf][1], al[mf][2], al[mf][3],
                         bh[nf][0], bh[nf][1]);
            }
    }

    // epilogue: write g_xw[v][row][col]
#pragma unroll
    for (int mf = 0; mf < 4; mf++) {
        int r0 = m0 + mf * 16 + g;
        int r1 = r0 + 8;
#pragma unroll
        for (int nf = 0; nf < 6; nf++) {
            int ng = n0 + nf * 8 + tg * 2;
            int v = ng >> 6;
            int col = ng & 63;
            float* base = g_xw + (size_t)v * N_NODES * NHID + col;
            if (r0 < N_NODES)
                *(float2*)(base + (size_t)r0 * NHID) = make_float2(acc[mf][nf][0], acc[mf][nf][1]);
            if (r1 < N_NODES)
                *(float2*)(base + (size_t)r1 * NHID) = make_float2(acc[mf][nf][2], acc[mf][nf][3]);
        }
    }
}

// ---------------- gather1 ----------------
__global__ void k_gather1(float* __restrict__ out,
                          const float* __restrict__ b1a, const float* __restrict__ b1b,
                          const float* __restrict__ b1c,
                          const float* __restrict__ W2a, const float* __restrict__ W2b,
                          const float* __restrict__ W2c,
                          const float* __restrict__ b2a, const float* __restrict__ b2b,
                          const float* __restrict__ b2c) {
    int gtid = blockIdx.x * blockDim.x + threadIdx.x;
    int node = gtid >> 5;
    int lane = gtid & 31;
    if (node >= N_NODES) return;

    float2 fsum = make_float2(0.f, 0.f);
    float selfsum = 0.f;
#pragma unroll
    for (int v = 0; v < 3; v++) {
        const float* b1 = (v == 0) ? b1a : (v == 1) ? b1b : b1c;
        const float* W2 = (v == 0) ? W2a : (v == 1) ? W2b : W2c;
        int nv = v * N_NODES + node;
        const float2* xwv = (const float2*)g_xw + (size_t)v * N_NODES * 32;

        float d1 = g_dinv[2 * nv + 0];
        float d2 = g_dinv[2 * nv + 1];
        float2 self = xwv[(size_t)node * 32 + lane];
        float sc = d1 * d1;
        float2 acc = make_float2(self.x * sc, self.y * sc);

        int base = g_off[nv];
        int cnt  = g_degI[nv];
        for (int e = 0; e < cnt; e++) {
            int4 p = g_ed[base + e];
            float c = __int_as_float(p.y);
            float2 m = xwv[(size_t)p.x * 32 + lane];
            acc.x = fmaf(m.x, c, acc.x);
            acc.y = fmaf(m.y, c, acc.y);
        }

        float h0 = fmaxf(acc.x + b1[lane * 2 + 0], 0.f);
        float h1 = fmaxf(acc.y + b1[lane * 2 + 1], 0.f);
        fsum.x += h0;
        fsum.y += h1;
        float p = h0 * W2[lane * 2 + 0] + h1 * W2[lane * 2 + 1];
#pragma unroll
        for (int o = 16; o > 0; o >>= 1) p += __shfl_xor_sync(0xffffffffu, p, o);
        if (lane == 0) g_hw[nv] = p;
        selfsum = fmaf(p, d2 * d2, selfsum);
    }
    *(float2*)(out + N_NODES + (size_t)node * NHID + lane * 2) = fsum;
    if (lane == 0) out[node] = selfsum + b2a[0] + b2b[0] + b2c[0];
}

// ---------------- gather2 ----------------
__global__ void k_gather2(float* __restrict__ out) {
    int gtid = blockIdx.x * blockDim.x + threadIdx.x;
    int node = gtid >> 5;
    int lane = gtid & 31;
    if (node >= N_NODES) return;

    float add = 0.f;
#pragma unroll
    for (int v = 0; v < 3; v++) {
        int nv = v * N_NODES + node;
        int base = g_off[nv];
        int cnt  = g_degI[nv];
        const float* hwv = g_hw + v * N_NODES;
        for (int e = lane; e < cnt; e += 32) {
            int4 p = g_ed[base + e];
            add = fmaf(hwv[p.x], __int_as_float(p.z), add);
        }
    }
#pragma unroll
    for (int o = 16; o > 0; o >>= 1) add += __shfl_xor_sync(0xffffffffu, add, o);
    if (lane == 0) out[node] += add;
}

// ---------------- launch ----------------
extern "C" void kernel_launch(void* const* d_in, const int* in_sizes, int n_in,
                              void* d_out, int out_size) {
    const float* x   = (const float*)d_in[0];
    const int*   ei0 = (const int*)d_in[1];
    const int*   ei1 = (const int*)d_in[2];
    const int*   ei2 = (const int*)d_in[3];
    const float* w0  = (const float*)d_in[4];
    const float* w1  = (const float*)d_in[5];
    const float* w2  = (const float*)d_in[6];
    const float* W1a = (const float*)d_in[7];
    const float* b1a = (const float*)d_in[8];
    const float* W2a = (const float*)d_in[9];
    const float* b2a = (const float*)d_in[10];
    const float* W1b = (const float*)d_in[11];
    const float* b1b = (const float*)d_in[12];
    const float* W2b = (const float*)d_in[13];
    const float* b2b = (const float*)d_in[14];
    const float* W1c = (const float*)d_in[15];
    const float* b1c = (const float*)d_in[16];
    const float* W2c = (const float*)d_in[17];
    const float* b2c = (const float*)d_in[18];
    float* out = (float*)d_out;

    k_zero<<<NBLK, 256>>>();
    k_prepX<<<(N_NODES * FIN / 4 + 255) / 256, 256>>>(x);
    k_prepW<<<(192 * FIN + 255) / 256, 256>>>(W1a, W1b, W1c);
    k_deg<<<dim3((N_EDGES + 255) / 256, 3), 256>>>(ei0, ei1, ei2, w0, w1, w2);
    k_scan1<<<NBLK, 256>>>();
    k_scan2<<<1, 1024>>>();
    k_scan3<<<NBLK, 256>>>();
    k_fill<<<dim3((N_EDGES + 255) / 256, 3), 256>>>(ei0, ei1, ei2, w0, w1, w2);
    k_gemm_mma<<<(N_NODES + 127) / 128, 256>>>();
    k_gather1<<<(N_NODES * 32 + 255) / 256, 256>>>(out, b1a, b1b, b1c,
                                                   W2a, W2b, W2c, b2a, b2b, b2c);
    k_gather2<<<(N_NODES * 32 + 255) / 256, 256>>>(out);
}

// round 5
// speedup vs baseline: 1.2443x; 1.0561x over previous
#include <cuda_runtime.h>
#include <cuda_bf16.h>
#include <cstdint>
#include <cstddef>

#define N_NODES 50000
#define N_EDGES 800000
#define FIN     256
#define NHID    64
#define NV      (3 * N_NODES)
#define NBLK    ((NV + 255) / 256)

// ---------------- device scratch (static, allocation-free) ----------------
__device__ float g_xw  [3 * N_NODES * NHID];
__device__ float g_degF[NV * 2];                 // interleaved {degW, count}
__device__ int   g_degI[NV];
__device__ float g_dinv[NV * 2];
__device__ float g_hw  [NV];
__device__ int   g_off [NV];
__device__ int   g_cur [NV];
__device__ int4  g_ed  [3 * N_EDGES];            // {src, c1-bits, c2-bits, 0}
__device__ int   g_bsum[1024];
__device__ __nv_bfloat16 g_xhi[(size_t)N_NODES * FIN];
__device__ __nv_bfloat16 g_xlo[(size_t)N_NODES * FIN];
__device__ __nv_bfloat16 g_whi[192 * FIN];       // [n_global][k]
__device__ __nv_bfloat16 g_wlo[192 * FIN];

// ---------------- init: {degW=1 (self loop), count=0} ----------------
__global__ void k_zero() {
    int i = blockIdx.x * blockDim.x + threadIdx.x;
    if (i < NV) ((float2*)g_degF)[i] = make_float2(1.0f, 0.0f);
}

// ---------------- x -> bf16 hi/lo split ----------------
__global__ void k_prepX(const float* __restrict__ x) {
    int i = blockIdx.x * blockDim.x + threadIdx.x;
    if (i >= N_NODES * FIN / 4) return;
    float4 a = ((const float4*)x)[i];
    __nv_bfloat16 h0 = __float2bfloat16_rn(a.x);
    __nv_bfloat16 h1 = __float2bfloat16_rn(a.y);
    __nv_bfloat16 h2 = __float2bfloat16_rn(a.z);
    __nv_bfloat16 h3 = __float2bfloat16_rn(a.w);
    __nv_bfloat16 l0 = __float2bfloat16_rn(a.x - __bfloat162float(h0));
    __nv_bfloat16 l1 = __float2bfloat16_rn(a.y - __bfloat162float(h1));
    __nv_bfloat16 l2 = __float2bfloat16_rn(a.z - __bfloat162float(h2));
    __nv_bfloat16 l3 = __float2bfloat16_rn(a.w - __bfloat162float(h3));
    ((ushort4*)g_xhi)[i] = make_ushort4(__bfloat16_as_ushort(h0), __bfloat16_as_ushort(h1),
                                        __bfloat16_as_ushort(h2), __bfloat16_as_ushort(h3));
    ((ushort4*)g_xlo)[i] = make_ushort4(__bfloat16_as_ushort(l0), __bfloat16_as_ushort(l1),
                                        __bfloat16_as_ushort(l2), __bfloat16_as_ushort(l3));
}

// ---------------- W -> transposed bf16 hi/lo ----------------
__global__ void k_prepW(const float* __restrict__ Wa, const float* __restrict__ Wb,
                        const float* __restrict__ Wc) {
    int idx = blockIdx.x * blockDim.x + threadIdx.x;
    if (idx >= 192 * FIN) return;
    int ng = idx >> 8;
    int k  = idx & 255;
    int v  = ng >> 6;
    int n  = ng & 63;
    const float* W = (v == 0) ? Wa : (v == 1) ? Wb : Wc;
    float f = W[k * NHID + n];
    __nv_bfloat16 h = __float2bfloat16_rn(f);
    __nv_bfloat16 l = __float2bfloat16_rn(f - __bfloat162float(h));
    g_whi[idx] = h;
    g_wlo[idx] = l;
}

// ---------------- degree accumulation: single float2 atomic ----------------
__global__ void k_deg(const int* __restrict__ ei0, const int* __restrict__ ei1,
                      const int* __restrict__ ei2,
                      const float* __restrict__ w0, const float* __restrict__ w1,
                      const float* __restrict__ w2) {
    int v = blockIdx.y;
    const int*   ei = (v == 0) ? ei0 : (v == 1) ? ei1 : ei2;
    const float* w  = (v == 0) ? w0  : (v == 1) ? w1  : w2;
    int e = blockIdx.x * blockDim.x + threadIdx.x;
    if (e >= N_EDGES) return;
    int nv = v * N_NODES + ei[N_EDGES + e];
    atomicAdd((float2*)&g_degF[2 * nv], make_float2(w[e], 1.0f));
}

// ---------------- scans ----------------
__global__ void k_scan1() {
    __shared__ int s[256];
    int t = threadIdx.x;
    int i = blockIdx.x * 256 + t;
    s[t] = (i < NV) ? (int)g_degF[2 * i + 1] : 0;
    __syncthreads();
#pragma unroll
    for (int o = 128; o > 0; o >>= 1) {
        if (t < o) s[t] += s[t + o];
        __syncthreads();
    }
    if (t == 0) g_bsum[blockIdx.x] = s[0];
}

__global__ void k_scan2() {
    __shared__ int s[1024];
    int t = threadIdx.x;
    int v = (t < NBLK) ? g_bsum[t] : 0;
    s[t] = v;
    __syncthreads();
#pragma unroll
    for (int o = 1; o < 1024; o <<= 1) {
        int x = (t >= o) ? s[t - o] : 0;
        __syncthreads();
        s[t] += x;
        __syncthreads();
    }
    if (t < NBLK) g_bsum[t] = s[t] - v;
}

__global__ void k_scan3() {
    __shared__ int s[256];
    int t = threadIdx.x;
    int i = blockIdx.x * 256 + t;
    int v = (i < NV) ? (int)g_degF[2 * i + 1] : 0;
    s[t] = v;
    __syncthreads();
#pragma unroll
    for (int o = 1; o < 256; o <<= 1) {
        int x = (t >= o) ? s[t - o] : 0;
        __syncthreads();
        s[t] += x;
        __syncthreads();
    }
    if (i < NV) {
        int off = g_bsum[blockIdx.x] + s[t] - v;
        g_off[i] = off;
        g_cur[i] = off;
        g_degI[i] = v;
        g_dinv[2 * i + 0] = rsqrtf(g_degF[2 * i]);
        g_dinv[2 * i + 1] = rsqrtf((float)(v + 1));
    }
}

// ---------------- CSR fill ----------------
__global__ void k_fill(const int* __restrict__ ei0, const int* __restrict__ ei1,
                       const int* __restrict__ ei2,
                       const float* __restrict__ w0, const float* __restrict__ w1,
                       const float* __restrict__ w2) {
    int v = blockIdx.y;
    const int*   ei = (v == 0) ? ei0 : (v == 1) ? ei1 : ei2;
    const float* w  = (v == 0) ? w0  : (v == 1) ? w1  : w2;
    int e = blockIdx.x * blockDim.x + threadIdx.x;
    if (e >= N_EDGES) return;
    int s = ei[e], d = ei[N_EDGES + e];
    int nv = v * N_NODES + d;
    const float2* dv = (const float2*)g_dinv;
    float2 ds = dv[v * N_NODES + s];
    float2 dd = dv[nv];
    float c1 = ds.x * w[e] * dd.x;
    float c2 = ds.y * dd.y;
    int slot = atomicAdd(&g_cur[nv], 1);
    g_ed[slot] = make_int4(s, __float_as_int(c1), __float_as_int(c2), 0);
}

// ---------------- bf16 mma GEMM ----------------
__device__ __forceinline__ void mma_bf16(float* d, uint32_t a0, uint32_t a1,
                                         uint32_t a2, uint32_t a3,
                                         uint32_t b0, uint32_t b1) {
    asm volatile("mma.sync.aligned.m16n8k16.row.col.f32.bf16.bf16.f32 "
                 "{%0,%1,%2,%3}, {%4,%5,%6,%7}, {%8,%9}, {%0,%1,%2,%3};"
                 : "+f"(d[0]), "+f"(d[1]), "+f"(d[2]), "+f"(d[3])
                 : "r"(a0), "r"(a1), "r"(a2), "r"(a3), "r"(b0), "r"(b1));
}

__global__ __launch_bounds__(256, 1) void k_gemm_mma() {
    int tid  = threadIdx.x;
    int w    = tid >> 5;
    int lane = tid & 31;
    int g    = lane >> 2;
    int tg   = lane & 3;
    int m0   = blockIdx.x * 128 + (w >> 2) * 64;
    int n0   = (w & 3) * 48;

    float acc[4][6][4];
#pragma unroll
    for (int mf = 0; mf < 4; mf++)
#pragma unroll
        for (int nf = 0; nf < 6; nf++)
#pragma unroll
            for (int j = 0; j < 4; j++) acc[mf][nf][j] = 0.f;

    int rbase[8];
#pragma unroll
    for (int mf = 0; mf < 4; mf++) {
        int r0 = m0 + mf * 16 + g;
        int r1 = r0 + 8;
        rbase[mf * 2 + 0] = min(r0, N_NODES - 1) * FIN;
        rbase[mf * 2 + 1] = min(r1, N_NODES - 1) * FIN;
    }

#pragma unroll 1
    for (int kc = 0; kc < 16; kc++) {
        int ka = kc * 16 + tg * 2;

        uint32_t ah[4][4], al[4][4];
#pragma unroll
        for (int mf = 0; mf < 4; mf++) {
            const uint32_t* h0 = (const uint32_t*)(g_xhi + rbase[mf * 2 + 0] + ka);
            const uint32_t* h1 = (const uint32_t*)(g_xhi + rbase[mf * 2 + 1] + ka);
            const uint32_t* l0 = (const uint32_t*)(g_xlo + rbase[mf * 2 + 0] + ka);
            const uint32_t* l1 = (const uint32_t*)(g_xlo + rbase[mf * 2 + 1] + ka);
            ah[mf][0] = h0[0]; ah[mf][1] = h1[0]; ah[mf][2] = h0[4]; ah[mf][3] = h1[4];
            al[mf][0] = l0[0]; al[mf][1] = l1[0]; al[mf][2] = l0[4]; al[mf][3] = l1[4];
        }
        uint32_t bh[6][2], bl[6][2];
#pragma unroll
        for (int nf = 0; nf < 6; nf++) {
            int ng = n0 + nf * 8 + g;
            const uint32_t* bhp = (const uint32_t*)(g_whi + ng * FIN + ka);
            const uint32_t* blp = (const uint32_t*)(g_wlo + ng * FIN + ka);
            bh[nf][0] = bhp[0]; bh[nf][1] = bhp[4];
            bl[nf][0] = blp[0]; bl[nf][1] = blp[4];
        }
#pragma unroll
        for (int mf = 0; mf < 4; mf++)
#pragma unroll
            for (int nf = 0; nf < 6; nf++) {
                mma_bf16(acc[mf][nf], ah[mf][0], ah[mf][1], ah[mf][2], ah[mf][3],
                         bh[nf][0], bh[nf][1]);
                mma_bf16(acc[mf][nf], ah[mf][0], ah[mf][1], ah[mf][2], ah[mf][3],
                         bl[nf][0], bl[nf][1]);
                mma_bf16(acc[mf][nf], al[mf][0], al[mf][1], al[mf][2], al[mf][3],
                         bh[nf][0], bh[nf][1]);
            }
    }

#pragma unroll
    for (int mf = 0; mf < 4; mf++) {
        int r0 = m0 + mf * 16 + g;
        int r1 = r0 + 8;
#pragma unroll
        for (int nf = 0; nf < 6; nf++) {
            int ng = n0 + nf * 8 + tg * 2;
            int v = ng >> 6;
            int col = ng & 63;
            float* base = g_xw + (size_t)v * N_NODES * NHID + col;
            if (r0 < N_NODES)
                *(float2*)(base + (size_t)r0 * NHID) = make_float2(acc[mf][nf][0], acc[mf][nf][1]);
            if (r1 < N_NODES)
                *(float2*)(base + (size_t)r1 * NHID) = make_float2(acc[mf][nf][2], acc[mf][nf][3]);
        }
    }
}

// ---------------- gather1 ----------------
__global__ void k_gather1(float* __restrict__ out,
                          const float* __restrict__ b1a, const float* __restrict__ b1b,
                          const float* __restrict__ b1c,
                          const float* __restrict__ W2a, const float* __restrict__ W2b,
                          const float* __restrict__ W2c,
                          const float* __restrict__ b2a, const float* __restrict__ b2b,
                          const float* __restrict__ b2c) {
    int gtid = blockIdx.x * blockDim.x + threadIdx.x;
    int node = gtid >> 5;
    int lane = gtid & 31;
    if (node >= N_NODES) return;

    float2 fsum = make_float2(0.f, 0.f);
    float selfsum = 0.f;
#pragma unroll
    for (int v = 0; v < 3; v++) {
        const float* b1 = (v == 0) ? b1a : (v == 1) ? b1b : b1c;
        const float* W2 = (v == 0) ? W2a : (v == 1) ? W2b : W2c;
        int nv = v * N_NODES + node;
        const float2* xwv = (const float2*)g_xw + (size_t)v * N_NODES * 32;

        float d1 = g_dinv[2 * nv + 0];
        float d2 = g_dinv[2 * nv + 1];
        float2 self = xwv[(size_t)node * 32 + lane];
        float sc = d1 * d1;
        float2 acc = make_float2(self.x * sc, self.y * sc);

        int base = g_off[nv];
        int cnt  = g_degI[nv];
        for (int e = 0; e < cnt; e++) {
            int4 p = g_ed[base + e];
            float c = __int_as_float(p.y);
            float2 m = xwv[(size_t)p.x * 32 + lane];
            acc.x = fmaf(m.x, c, acc.x);
            acc.y = fmaf(m.y, c, acc.y);
        }

        float h0 = fmaxf(acc.x + b1[lane * 2 + 0], 0.f);
        float h1 = fmaxf(acc.y + b1[lane * 2 + 1], 0.f);
        fsum.x += h0;
        fsum.y += h1;
        float p = h0 * W2[lane * 2 + 0] + h1 * W2[lane * 2 + 1];
#pragma unroll
        for (int o = 16; o > 0; o >>= 1) p += __shfl_xor_sync(0xffffffffu, p, o);
        if (lane == 0) g_hw[nv] = p;
        selfsum = fmaf(p, d2 * d2, selfsum);
    }
    *(float2*)(out + N_NODES + (size_t)node * NHID + lane * 2) = fsum;
    if (lane == 0) out[node] = selfsum + b2a[0] + b2b[0] + b2c[0];
}

// ---------------- gather2 ----------------
__global__ void k_gather2(float* __restrict__ out) {
    int gtid = blockIdx.x * blockDim.x + threadIdx.x;
    int node = gtid >> 5;
    int lane = gtid & 31;
    if (node >= N_NODES) return;

    float add = 0.f;
#pragma unroll
    for (int v = 0; v < 3; v++) {
        int nv = v * N_NODES + node;
        int base = g_off[nv];
        int cnt  = g_degI[nv];
        const float* hwv = g_hw + v * N_NODES;
        for (int e = lane; e < cnt; e += 32) {
            int4 p = g_ed[base + e];
            add = fmaf(hwv[p.x], __int_as_float(p.z), add);
        }
    }
#pragma unroll
    for (int o = 16; o > 0; o >>= 1) add += __shfl_xor_sync(0xffffffffu, add, o);
    if (lane == 0) out[node] += add;
}

// ---------------- launch ----------------
extern "C" void kernel_launch(void* const* d_in, const int* in_sizes, int n_in,
                              void* d_out, int out_size) {
    const float* x   = (const float*)d_in[0];
    const int*   ei0 = (const int*)d_in[1];
    const int*   ei1 = (const int*)d_in[2];
    const int*   ei2 = (const int*)d_in[3];
    const float* w0  = (const float*)d_in[4];
    const float* w1  = (const float*)d_in[5];
    const float* w2  = (const float*)d_in[6];
    const float* W1a = (const float*)d_in[7];
    const float* b1a = (const float*)d_in[8];
    const float* W2a = (const float*)d_in[9];
    const float* b2a = (const float*)d_in[10];
    const float* W1b = (const float*)d_in[11];
    const float* b1b = (const float*)d_in[12];
    const float* W2b = (const float*)d_in[13];
    const float* b2b = (const float*)d_in[14];
    const float* W1c = (const float*)d_in[15];
    const float* b1c = (const float*)d_in[16];
    const float* W2c = (const float*)d_in[17];
    const float* b2c = (const float*)d_in[18];
    float* out = (float*)d_out;

    // order chosen so launch #6 (ncu -s 5 -c 1) is the GEMM
    k_zero<<<NBLK, 256>>>();                                             // 1
    k_prepX<<<(N_NODES * FIN / 4 + 255) / 256, 256>>>(x);                // 2
    k_prepW<<<(192 * FIN + 255) / 256, 256>>>(W1a, W1b, W1c);            // 3
    k_deg<<<dim3((N_EDGES + 255) / 256, 3), 256>>>(ei0, ei1, ei2, w0, w1, w2); // 4
    k_scan1<<<NBLK, 256>>>();                                            // 5
    k_gemm_mma<<<(N_NODES + 127) / 128, 256>>>();                        // 6 <- profiled
    k_scan2<<<1, 1024>>>();                                              // 7
    k_scan3<<<NBLK, 256>>>();                                            // 8
    k_fill<<<dim3((N_EDGES + 255) / 256, 3), 256>>>(ei0, ei1, ei2, w0, w1, w2); // 9
    k_gather1<<<(N_NODES * 32 + 255) / 256, 256>>>(out, b1a, b1b, b1c,
                                                   W2a, W2b, W2c, b2a, b2b, b2c); // 10
    k_gather2<<<(N_NODES * 32 + 255) / 256, 256>>>(out);                 // 11
}

// round 6
// speedup vs baseline: 1.4854x; 1.1938x over previous
#include <cuda_runtime.h>
#include <cuda_bf16.h>
#include <cstdint>
#include <cstddef>

#define N_NODES 50000
#define N_EDGES 800000
#define FIN     256
#define NHID    64
#define NV      (3 * N_NODES)
#define NBLK    ((NV + 255) / 256)

// ---------------- device scratch (static, allocation-free) ----------------
__device__ float g_xw  [3 * N_NODES * NHID];
__device__ float g_degF[NV * 2];                 // interleaved {degW, count}
__device__ int   g_degI[NV];
__device__ float g_dinv[NV * 2];
__device__ float g_hw  [NV];
__device__ int   g_off [NV];
__device__ int   g_cur [NV];
__device__ int4  g_ed  [3 * N_EDGES];            // {src, c1-bits, c2-bits, 0}
__device__ int   g_bsum[1024];
__device__ __align__(16) __nv_bfloat16 g_whi[192 * FIN];   // [n_global][k]
__device__ __align__(16) __nv_bfloat16 g_wlo[192 * FIN];

// ---------------- init: {degW=1 (self loop), count=0} ----------------
__global__ void k_zero() {
    int i = blockIdx.x * blockDim.x + threadIdx.x;
    if (i < NV) ((float2*)g_degF)[i] = make_float2(1.0f, 0.0f);
}

// ---------------- W -> transposed bf16 hi/lo ----------------
__global__ void k_prepW(const float* __restrict__ Wa, const float* __restrict__ Wb,
                        const float* __restrict__ Wc) {
    int idx = blockIdx.x * blockDim.x + threadIdx.x;
    if (idx >= 192 * FIN) return;
    int ng = idx >> 8;
    int k  = idx & 255;
    int v  = ng >> 6;
    int n  = ng & 63;
    const float* W = (v == 0) ? Wa : (v == 1) ? Wb : Wc;
    float f = W[k * NHID + n];
    __nv_bfloat16 h = __float2bfloat16_rn(f);
    __nv_bfloat16 l = __float2bfloat16_rn(f - __bfloat162float(h));
    g_whi[idx] = h;
    g_wlo[idx] = l;
}

// ---------------- degree accumulation: single float2 atomic ----------------
__global__ void k_deg(const int* __restrict__ ei0, const int* __restrict__ ei1,
                      const int* __restrict__ ei2,
                      const float* __restrict__ w0, const float* __restrict__ w1,
                      const float* __restrict__ w2) {
    int v = blockIdx.y;
    const int*   ei = (v == 0) ? ei0 : (v == 1) ? ei1 : ei2;
    const float* w  = (v == 0) ? w0  : (v == 1) ? w1  : w2;
    int e = blockIdx.x * blockDim.x + threadIdx.x;
    if (e >= N_EDGES) return;
    int nv = v * N_NODES + ei[N_EDGES + e];
    atomicAdd((float2*)&g_degF[2 * nv], make_float2(w[e], 1.0f));
}

// ---------------- scans ----------------
__global__ void k_scan1() {
    __shared__ int s[256];
    int t = threadIdx.x;
    int i = blockIdx.x * 256 + t;
    s[t] = (i < NV) ? (int)g_degF[2 * i + 1] : 0;
    __syncthreads();
#pragma unroll
    for (int o = 128; o > 0; o >>= 1) {
        if (t < o) s[t] += s[t + o];
        __syncthreads();
    }
    if (t == 0) g_bsum[blockIdx.x] = s[0];
}

__global__ void k_scan2() {
    __shared__ int s[1024];
    int t = threadIdx.x;
    int v = (t < NBLK) ? g_bsum[t] : 0;
    s[t] = v;
    __syncthreads();
#pragma unroll
    for (int o = 1; o < 1024; o <<= 1) {
        int x = (t >= o) ? s[t - o] : 0;
        __syncthreads();
        s[t] += x;
        __syncthreads();
    }
    if (t < NBLK) g_bsum[t] = s[t] - v;
}

__global__ void k_scan3() {
    __shared__ int s[256];
    int t = threadIdx.x;
    int i = blockIdx.x * 256 + t;
    int v = (i < NV) ? (int)g_degF[2 * i + 1] : 0;
    s[t] = v;
    __syncthreads();
#pragma unroll
    for (int o = 1; o < 256; o <<= 1) {
        int x = (t >= o) ? s[t - o] : 0;
        __syncthreads();
        s[t] += x;
        __syncthreads();
    }
    if (i < NV) {
        int off = g_bsum[blockIdx.x] + s[t] - v;
        g_off[i] = off;
        g_cur[i] = off;
        g_degI[i] = v;
        g_dinv[2 * i + 0] = rsqrtf(g_degF[2 * i]);
        g_dinv[2 * i + 1] = rsqrtf((float)(v + 1));
    }
}

// ---------------- CSR fill ----------------
__global__ void k_fill(const int* __restrict__ ei0, const int* __restrict__ ei1,
                       const int* __restrict__ ei2,
                       const float* __restrict__ w0, const float* __restrict__ w1,
                       const float* __restrict__ w2) {
    int v = blockIdx.y;
    const int*   ei = (v == 0) ? ei0 : (v == 1) ? ei1 : ei2;
    const float* w  = (v == 0) ? w0  : (v == 1) ? w1  : w2;
    int e = blockIdx.x * blockDim.x + threadIdx.x;
    if (e >= N_EDGES) return;
    int s = ei[e], d = ei[N_EDGES + e];
    int nv = v * N_NODES + d;
    const float2* dv = (const float2*)g_dinv;
    float2 ds = dv[v * N_NODES + s];
    float2 dd = dv[nv];
    float c1 = ds.x * w[e] * dd.x;
    float c2 = ds.y * dd.y;
    int slot = atomicAdd(&g_cur[nv], 1);
    g_ed[slot] = make_int4(s, __float_as_int(c1), __float_as_int(c2), 0);
}

// ---------------- bf16 mma GEMM, smem-staged + ldmatrix ----------------
__device__ __forceinline__ uint32_t smem_u32(const void* p) {
    uint32_t a;
    asm("{ .reg .u64 t; cvta.to.shared.u64 t, %1; cvt.u32.u64 %0, t; }" : "=r"(a) : "l"(p));
    return a;
}
__device__ __forceinline__ void mma_bf16(float* d, const uint32_t* a,
                                         uint32_t b0, uint32_t b1) {
    asm volatile("mma.sync.aligned.m16n8k16.row.col.f32.bf16.bf16.f32 "
                 "{%0,%1,%2,%3}, {%4,%5,%6,%7}, {%8,%9}, {%0,%1,%2,%3};"
                 : "+f"(d[0]), "+f"(d[1]), "+f"(d[2]), "+f"(d[3])
                 : "r"(a[0]), "r"(a[1]), "r"(a[2]), "r"(a[3]), "r"(b0), "r"(b1));
}
__device__ __forceinline__ void ldsm_x4(uint32_t* r, uint32_t addr) {
    asm volatile("ldmatrix.sync.aligned.m8n8.x4.shared.b16 {%0,%1,%2,%3}, [%4];"
                 : "=r"(r[0]), "=r"(r[1]), "=r"(r[2]), "=r"(r[3]) : "r"(addr));
}
__device__ __forceinline__ uint32_t pack_hi(float a, float b) {
    return (uint32_t)__bfloat16_as_ushort(__float2bfloat16_rn(a)) |
           ((uint32_t)__bfloat16_as_ushort(__float2bfloat16_rn(b)) << 16);
}
__device__ __forceinline__ uint32_t pack_lo(float a, float b) {
    float ra = a - __bfloat162float(__float2bfloat16_rn(a));
    float rb = b - __bfloat162float(__float2bfloat16_rn(b));
    return (uint32_t)__bfloat16_as_ushort(__float2bfloat16_rn(ra)) |
           ((uint32_t)__bfloat16_as_ushort(__float2bfloat16_rn(rb)) << 16);
}

#define A_ST   80                       // 64B data + 16B pad per 32-k row
#define ABUF   (128 * A_ST)             // 10240
#define BBUF   (192 * A_ST)             // 15360
#define BUFSZ  (2 * ABUF + 2 * BBUF)    // 51200
#define GSMEM  (2 * BUFSZ)              // 102400

__global__ __launch_bounds__(256, 1) void k_gemm_mma(const float* __restrict__ x) {
    extern __shared__ char smc[];
    uint32_t sb = smem_u32(smc);
    int tid  = threadIdx.x;
    int w    = tid >> 5;
    int lane = tid & 31;
    int warp_m = (w >> 2) * 64;
    int warp_n = (w & 3) * 48;
    int rowBlock = blockIdx.x * 128;

    float acc[4][6][4];
#pragma unroll
    for (int mf = 0; mf < 4; mf++)
#pragma unroll
        for (int nf = 0; nf < 6; nf++)
#pragma unroll
            for (int j = 0; j < 4; j++) acc[mf][nf][j] = 0.f;

    float4 aReg[4];
    uint4  bhReg[3], blReg[3];

    // ---- prefetch k-chunk 0 ----
#pragma unroll
    for (int i = 0; i < 4; i++) {
        int idx = tid + i * 256, r = idx >> 3, c4 = idx & 7;
        int grow = rowBlock + r;
        aReg[i] = (grow < N_NODES)
            ? *((const float4*)(x + (size_t)grow * FIN) + c4)
            : make_float4(0.f, 0.f, 0.f, 0.f);
    }
#pragma unroll
    for (int i = 0; i < 3; i++) {
        int idx = tid + i * 256, n = idx >> 2, c = idx & 3;
        bhReg[i] = *(const uint4*)(g_whi + n * FIN + c * 8);
        blReg[i] = *(const uint4*)(g_wlo + n * FIN + c * 8);
    }

    for (int kc = 0; kc < 8; kc++) {
        uint32_t Ah = sb + (kc & 1) * BUFSZ;
        uint32_t Al = Ah + ABUF;
        uint32_t Bh = Ah + 2 * ABUF;
        uint32_t Bl = Bh + BBUF;

        // ---- STS staged regs ----
#pragma unroll
        for (int i = 0; i < 4; i++) {
            int idx = tid + i * 256, r = idx >> 3, c4 = idx & 7;
            float4 a = aReg[i];
            uint32_t h01 = pack_hi(a.x, a.y), h23 = pack_hi(a.z, a.w);
            uint32_t l01 = pack_lo(a.x, a.y), l23 = pack_lo(a.z, a.w);
            uint32_t off = (uint32_t)(r * A_ST + c4 * 8);
            asm volatile("st.shared.v2.u32 [%0], {%1,%2};" :: "r"(Ah + off), "r"(h01), "r"(h23) : "memory");
            asm volatile("st.shared.v2.u32 [%0], {%1,%2};" :: "r"(Al + off), "r"(l01), "r"(l23) : "memory");
        }
#pragma unroll
        for (int i = 0; i < 3; i++) {
            int idx = tid + i * 256, n = idx >> 2, c = idx & 3;
            uint32_t off = (uint32_t)(n * A_ST + c * 16);
            uint4 vh = bhReg[i], vl = blReg[i];
            asm volatile("st.shared.v4.u32 [%0], {%1,%2,%3,%4};"
                         :: "r"(Bh + off), "r"(vh.x), "r"(vh.y), "r"(vh.z), "r"(vh.w) : "memory");
            asm volatile("st.shared.v4.u32 [%0], {%1,%2,%3,%4};"
                         :: "r"(Bl + off), "r"(vl.x), "r"(vl.y), "r"(vl.z), "r"(vl.w) : "memory");
        }
        __syncthreads();

        // ---- prefetch next chunk ----
        if (kc < 7) {
            int k0 = (kc + 1) * 32;
#pragma unroll
            for (int i = 0; i < 4; i++) {
                int idx = tid + i * 256, r = idx >> 3, c4 = idx & 7;
                int grow = rowBlock + r;
                aReg[i] = (grow < N_NODES)
                    ? *((const float4*)(x + (size_t)grow * FIN + k0) + c4)
                    : make_float4(0.f, 0.f, 0.f, 0.f);
            }
#pragma unroll
            for (int i = 0; i < 3; i++) {
                int idx = tid + i * 256, n = idx >> 2, c = idx & 3;
                bhReg[i] = *(const uint4*)(g_whi + n * FIN + k0 + c * 8);
                blReg[i] = *(const uint4*)(g_wlo + n * FIN + k0 + c * 8);
            }
        }

        // ---- mma over two k16 sub-chunks ----
        int lrow = lane & 15;
        int kcol = (lane >> 4) * 16;
#pragma unroll
        for (int sk = 0; sk < 2; sk++) {
            uint32_t koff = (uint32_t)(sk * 32 + kcol);
            uint32_t ah[4][4], al[4][4];
#pragma unroll
            for (int mf = 0; mf < 4; mf++) {
                uint32_t addr = Ah + (uint32_t)((warp_m + mf * 16 + lrow) * A_ST) + koff;
                ldsm_x4(ah[mf], addr);
                ldsm_x4(al[mf], addr + ABUF);
            }
            uint32_t bh[3][4], bl[3][4];
#pragma unroll
            for (int j = 0; j < 3; j++) {
                uint32_t addr = Bh + (uint32_t)((warp_n + j * 16 + lrow) * A_ST) + koff;
                ldsm_x4(bh[j], addr);
                ldsm_x4(bl[j], addr + BBUF);
            }
#pragma unroll
            for (int mf = 0; mf < 4; mf++)
#pragma unroll
                for (int nf = 0; nf < 6; nf++) {
                    int j = nf >> 1, hf = nf & 1;
                    mma_bf16(acc[mf][nf], ah[mf], bh[j][hf], bh[j][2 + hf]);
                    mma_bf16(acc[mf][nf], ah[mf], bl[j][hf], bl[j][2 + hf]);
                    mma_bf16(acc[mf][nf], al[mf], bh[j][hf], bh[j][2 + hf]);
                }
        }
        __syncthreads();
    }

    // ---- epilogue ----
    int g  = lane >> 2;
    int tg = lane & 3;
#pragma unroll
    for (int mf = 0; mf < 4; mf++) {
        int r0 = rowBlock + warp_m + mf * 16 + g;
        int r1 = r0 + 8;
#pragma unroll
        for (int nf = 0; nf < 6; nf++) {
            int ng = warp_n + nf * 8 + tg * 2;
            int v = ng >> 6;
            int col = ng & 63;
            float* base = g_xw + (size_t)v * N_NODES * NHID + col;
            if (r0 < N_NODES)
                *(float2*)(base + (size_t)r0 * NHID) = make_float2(acc[mf][nf][0], acc[mf][nf][1]);
            if (r1 < N_NODES)
                *(float2*)(base + (size_t)r1 * NHID) = make_float2(acc[mf][nf][2], acc[mf][nf][3]);
        }
    }
}

// ---------------- gather1 ----------------
__global__ void k_gather1(float* __restrict__ out,
                          const float* __restrict__ b1a, const float* __restrict__ b1b,
                          const float* __restrict__ b1c,
                          const float* __restrict__ W2a, const float* __restrict__ W2b,
                          const float* __restrict__ W2c,
                          const float* __restrict__ b2a, const float* __restrict__ b2b,
                          const float* __restrict__ b2c) {
    int gtid = blockIdx.x * blockDim.x + threadIdx.x;
    int node = gtid >> 5;
    int lane = gtid & 31;
    if (node >= N_NODES) return;

    float2 fsum = make_float2(0.f, 0.f);
    float selfsum = 0.f;
#pragma unroll
    for (int v = 0; v < 3; v++) {
        const float* b1 = (v == 0) ? b1a : (v == 1) ? b1b : b1c;
        const float* W2 = (v == 0) ? W2a : (v == 1) ? W2b : W2c;
        int nv = v * N_NODES + node;
        const float2* xwv = (const float2*)g_xw + (size_t)v * N_NODES * 32;

        float d1 = g_dinv[2 * nv + 0];
        float d2 = g_dinv[2 * nv + 1];
        float2 self = xwv[(size_t)node * 32 + lane];
        float sc = d1 * d1;
        float2 acc = make_float2(self.x * sc, self.y * sc);

        int base = g_off[nv];
        int cnt  = g_degI[nv];
        for (int e = 0; e < cnt; e++) {
            int4 p = g_ed[base + e];
            float c = __int_as_float(p.y);
            float2 m = xwv[(size_t)p.x * 32 + lane];
            acc.x = fmaf(m.x, c, acc.x);
            acc.y = fmaf(m.y, c, acc.y);
        }

        float h0 = fmaxf(acc.x + b1[lane * 2 + 0], 0.f);
        float h1 = fmaxf(acc.y + b1[lane * 2 + 1], 0.f);
        fsum.x += h0;
        fsum.y += h1;
        float p = h0 * W2[lane * 2 + 0] + h1 * W2[lane * 2 + 1];
#pragma unroll
        for (int o = 16; o > 0; o >>= 1) p += __shfl_xor_sync(0xffffffffu, p, o);
        if (lane == 0) g_hw[nv] = p;
        selfsum = fmaf(p, d2 * d2, selfsum);
    }
    *(float2*)(out + N_NODES + (size_t)node * NHID + lane * 2) = fsum;
    if (lane == 0) out[node] = selfsum + b2a[0] + b2b[0] + b2c[0];
}

// ---------------- gather2 ----------------
__global__ void k_gather2(float* __restrict__ out) {
    int gtid = blockIdx.x * blockDim.x + threadIdx.x;
    int node = gtid >> 5;
    int lane = gtid & 31;
    if (node >= N_NODES) return;

    float add = 0.f;
#pragma unroll
    for (int v = 0; v < 3; v++) {
        int nv = v * N_NODES + node;
        int base = g_off[nv];
        int cnt  = g_degI[nv];
        const float* hwv = g_hw + v * N_NODES;
        for (int e = lane; e < cnt; e += 32) {
            int4 p = g_ed[base + e];
            add = fmaf(hwv[p.x], __int_as_float(p.z), add);
        }
    }
#pragma unroll
    for (int o = 16; o > 0; o >>= 1) add += __shfl_xor_sync(0xffffffffu, add, o);
    if (lane == 0) out[node] += add;
}

// ---------------- launch ----------------
extern "C" void kernel_launch(void* const* d_in, const int* in_sizes, int n_in,
                              void* d_out, int out_size) {
    const float* x   = (const float*)d_in[0];
    const int*   ei0 = (const int*)d_in[1];
    const int*   ei1 = (const int*)d_in[2];
    const int*   ei2 = (const int*)d_in[3];
    const float* w0  = (const float*)d_in[4];
    const float* w1  = (const float*)d_in[5];
    const float* w2  = (const float*)d_in[6];
    const float* W1a = (const float*)d_in[7];
    const float* b1a = (const float*)d_in[8];
    const float* W2a = (const float*)d_in[9];
    const float* b2a = (const float*)d_in[10];
    const float* W1b = (const float*)d_in[11];
    const float* b1b = (const float*)d_in[12];
    const float* W2b = (const float*)d_in[13];
    const float* b2b = (const float*)d_in[14];
    const float* W1c = (const float*)d_in[15];
    const float* b1c = (const float*)d_in[16];
    const float* W2c = (const float*)d_in[17];
    const float* b2c = (const float*)d_in[18];
    float* out = (float*)d_out;

    static int smem_set = 0;
    if (!smem_set) {
        cudaFuncSetAttribute(k_gemm_mma, cudaFuncAttributeMaxDynamicSharedMemorySize, GSMEM);
        smem_set = 1;
    }

    // launch #4 gets profiled by ncu -> put the GEMM there
    k_zero<<<NBLK, 256>>>();                                                   // 1
    k_prepW<<<(192 * FIN + 255) / 256, 256>>>(W1a, W1b, W1c);                  // 2
    k_deg<<<dim3((N_EDGES + 255) / 256, 3), 256>>>(ei0, ei1, ei2, w0, w1, w2); // 3
    k_gemm_mma<<<(N_NODES + 127) / 128, 256, GSMEM>>>(x);                      // 4 <- profiled
    k_scan1<<<NBLK, 256>>>();                                                  // 5
    k_scan2<<<1, 1024>>>();                                                    // 6
    k_scan3<<<NBLK, 256>>>();                                                  // 7
    k_fill<<<dim3((N_EDGES + 255) / 256, 3), 256>>>(ei0, ei1, ei2, w0, w1, w2);// 8
    k_gather1<<<(N_NODES * 32 + 255) / 256, 256>>>(out, b1a, b1b, b1c,
                                                   W2a, W2b, W2c, b2a, b2b, b2c); // 9
    k_gather2<<<(N_NODES * 32 + 255) / 256, 256>>>(out);                       // 10
}

// round 7
// speedup vs baseline: 1.5435x; 1.0391x over previous
#include <cuda_runtime.h>
#include <cuda_bf16.h>
#include <cstdint>
#include <cstddef>

#define N_NODES 50000
#define N_EDGES 800000
#define FIN     256
#define NHID    64
#define NV      (3 * N_NODES)
#define NBLK    ((NV + 255) / 256)

// ---------------- device scratch (static, allocation-free) ----------------
__device__ float g_xw  [3 * N_NODES * NHID];
__device__ float g_degF[NV * 2];                 // interleaved {degW, count}
__device__ int   g_degI[NV];
__device__ float g_dinv[NV * 2];
__device__ float g_hw  [NV];
__device__ int   g_off [NV];
__device__ int   g_cur [NV];
__device__ int4  g_ed  [3 * N_EDGES];            // {src, c1-bits, c2-bits, 0}
__device__ int   g_bsum[1024];
__device__ __align__(16) __nv_bfloat16 g_whi[192 * FIN];   // [n_global][k]
__device__ __align__(16) __nv_bfloat16 g_wlo[192 * FIN];

// ---------------- init: {degW=1 (self loop), count=0} ----------------
__global__ void k_zero() {
    int i = blockIdx.x * blockDim.x + threadIdx.x;
    if (i < NV) ((float2*)g_degF)[i] = make_float2(1.0f, 0.0f);
}

// ---------------- W -> transposed bf16 hi/lo ----------------
__global__ void k_prepW(const float* __restrict__ Wa, const float* __restrict__ Wb,
                        const float* __restrict__ Wc) {
    int idx = blockIdx.x * blockDim.x + threadIdx.x;
    if (idx >= 192 * FIN) return;
    int ng = idx >> 8;
    int k  = idx & 255;
    int v  = ng >> 6;
    int n  = ng & 63;
    const float* W = (v == 0) ? Wa : (v == 1) ? Wb : Wc;
    float f = W[k * NHID + n];
    __nv_bfloat16 h = __float2bfloat16_rn(f);
    __nv_bfloat16 l = __float2bfloat16_rn(f - __bfloat162float(h));
    g_whi[idx] = h;
    g_wlo[idx] = l;
}

// ---------------- degree accumulation: single float2 atomic ----------------
__global__ void k_deg(const int* __restrict__ ei0, const int* __restrict__ ei1,
                      const int* __restrict__ ei2,
                      const float* __restrict__ w0, const float* __restrict__ w1,
                      const float* __restrict__ w2) {
    int v = blockIdx.y;
    const int*   ei = (v == 0) ? ei0 : (v == 1) ? ei1 : ei2;
    const float* w  = (v == 0) ? w0  : (v == 1) ? w1  : w2;
    int e = blockIdx.x * blockDim.x + threadIdx.x;
    if (e >= N_EDGES) return;
    int nv = v * N_NODES + ei[N_EDGES + e];
    atomicAdd((float2*)&g_degF[2 * nv], make_float2(w[e], 1.0f));
}

// ---------------- scans ----------------
__global__ void k_scan1() {
    __shared__ int s[256];
    int t = threadIdx.x;
    int i = blockIdx.x * 256 + t;
    s[t] = (i < NV) ? (int)g_degF[2 * i + 1] : 0;
    __syncthreads();
#pragma unroll
    for (int o = 128; o > 0; o >>= 1) {
        if (t < o) s[t] += s[t + o];
        __syncthreads();
    }
    if (t == 0) g_bsum[blockIdx.x] = s[0];
}

__global__ void k_scan2() {
    __shared__ int s[1024];
    int t = threadIdx.x;
    int v = (t < NBLK) ? g_bsum[t] : 0;
    s[t] = v;
    __syncthreads();
#pragma unroll
    for (int o = 1; o < 1024; o <<= 1) {
        int x = (t >= o) ? s[t - o] : 0;
        __syncthreads();
        s[t] += x;
        __syncthreads();
    }
    if (t < NBLK) g_bsum[t] = s[t] - v;
}

__global__ void k_scan3() {
    __shared__ int s[256];
    int t = threadIdx.x;
    int i = blockIdx.x * 256 + t;
    int v = (i < NV) ? (int)g_degF[2 * i + 1] : 0;
    s[t] = v;
    __syncthreads();
#pragma unroll
    for (int o = 1; o < 256; o <<= 1) {
        int x = (t >= o) ? s[t - o] : 0;
        __syncthreads();
        s[t] += x;
        __syncthreads();
    }
    if (i < NV) {
        int off = g_bsum[blockIdx.x] + s[t] - v;
        g_off[i] = off;
        g_cur[i] = off;
        g_degI[i] = v;
        g_dinv[2 * i + 0] = rsqrtf(g_degF[2 * i]);
        g_dinv[2 * i + 1] = rsqrtf((float)(v + 1));
    }
}

// ---------------- CSR fill ----------------
__global__ void k_fill(const int* __restrict__ ei0, const int* __restrict__ ei1,
                       const int* __restrict__ ei2,
                       const float* __restrict__ w0, const float* __restrict__ w1,
                       const float* __restrict__ w2) {
    int v = blockIdx.y;
    const int*   ei = (v == 0) ? ei0 : (v == 1) ? ei1 : ei2;
    const float* w  = (v == 0) ? w0  : (v == 1) ? w1  : w2;
    int e = blockIdx.x * blockDim.x + threadIdx.x;
    if (e >= N_EDGES) return;
    int s = ei[e], d = ei[N_EDGES + e];
    int nv = v * N_NODES + d;
    const float2* dv = (const float2*)g_dinv;
    float2 ds = dv[v * N_NODES + s];
    float2 dd = dv[nv];
    float c1 = ds.x * w[e] * dd.x;
    float c2 = ds.y * dd.y;
    int slot = atomicAdd(&g_cur[nv], 1);
    g_ed[slot] = make_int4(s, __float_as_int(c1), __float_as_int(c2), 0);
}

// ---------------- bf16 mma GEMM, 64x192 tile, occ-2 ----------------
__device__ __forceinline__ uint32_t smem_u32(const void* p) {
    uint32_t a;
    asm("{ .reg .u64 t; cvta.to.shared.u64 t, %1; cvt.u32.u64 %0, t; }" : "=r"(a) : "l"(p));
    return a;
}
__device__ __forceinline__ void mma_bf16(float* d, const uint32_t* a,
                                         uint32_t b0, uint32_t b1) {
    asm volatile("mma.sync.aligned.m16n8k16.row.col.f32.bf16.bf16.f32 "
                 "{%0,%1,%2,%3}, {%4,%5,%6,%7}, {%8,%9}, {%0,%1,%2,%3};"
                 : "+f"(d[0]), "+f"(d[1]), "+f"(d[2]), "+f"(d[3])
                 : "r"(a[0]), "r"(a[1]), "r"(a[2]), "r"(a[3]), "r"(b0), "r"(b1));
}
__device__ __forceinline__ void ldsm_x4(uint32_t* r, uint32_t addr) {
    asm volatile("ldmatrix.sync.aligned.m8n8.x4.shared.b16 {%0,%1,%2,%3}, [%4];"
                 : "=r"(r[0]), "=r"(r[1]), "=r"(r[2]), "=r"(r[3]) : "r"(addr));
}
__device__ __forceinline__ uint32_t pack_hi(float a, float b) {
    return (uint32_t)__bfloat16_as_ushort(__float2bfloat16_rn(a)) |
           ((uint32_t)__bfloat16_as_ushort(__float2bfloat16_rn(b)) << 16);
}
__device__ __forceinline__ uint32_t pack_lo(float a, float b) {
    float ra = a - __bfloat162float(__float2bfloat16_rn(a));
    float rb = b - __bfloat162float(__float2bfloat16_rn(b));
    return (uint32_t)__bfloat16_as_ushort(__float2bfloat16_rn(ra)) |
           ((uint32_t)__bfloat16_as_ushort(__float2bfloat16_rn(rb)) << 16);
}
#define CP_ASYNC16(dst, src) \
    asm volatile("cp.async.ca.shared.global [%0], [%1], 16;" :: "r"(dst), "l"(src) : "memory")
#define CP_COMMIT() asm volatile("cp.async.commit_group;" ::: "memory")
#define CP_WAIT0()  asm volatile("cp.async.wait_group 0;" ::: "memory")

#define A_ST   80                       // 64B data + 16B pad per 32-k row
#define ABUF   (2 * 64 * A_ST)          // A hi+lo: 10240
#define BBUF   (192 * A_ST)             // one B term: 15360
#define BUFSZ  (ABUF + 2 * BBUF)        // 40960
#define GSMEM  (2 * BUFSZ)              // 81920

__global__ __launch_bounds__(256, 2) void k_gemm_mma(const float* __restrict__ x) {
    extern __shared__ char smc[];
    uint32_t sb = smem_u32(smc);
    int tid  = threadIdx.x;
    int w    = tid >> 5;
    int lane = tid & 31;
    int warp_m = (w >> 2) * 32;          // {0, 32}
    int warp_n = (w & 3) * 48;           // {0, 48, 96, 144}
    int rowBlock = blockIdx.x * 64;

    float acc[2][6][4];
#pragma unroll
    for (int mf = 0; mf < 2; mf++)
#pragma unroll
        for (int nf = 0; nf < 6; nf++)
#pragma unroll
            for (int j = 0; j < 4; j++) acc[mf][nf][j] = 0.f;

    float4 aReg[2];

    // A-tile thread mapping: 64 rows x 8 float4 = 512 slots, 2 per thread
    int ar0 = tid >> 3, ac0 = tid & 7;            // slot tid
    int ar1 = (tid + 256) >> 3, ac1 = ac0;        // slot tid+256
    // B cp.async mapping: 768 16B-chunks per term, 3 per thread
    // chunk idx -> n = idx>>2, c = idx&3

    // ---- prefetch chunk 0 ----
    {
        int g0 = rowBlock + ar0, g1 = rowBlock + ar1;
        aReg[0] = (g0 < N_NODES) ? *((const float4*)(x + (size_t)g0 * FIN) + ac0)
                                 : make_float4(0.f, 0.f, 0.f, 0.f);
        aReg[1] = (g1 < N_NODES) ? *((const float4*)(x + (size_t)g1 * FIN) + ac1)
                                 : make_float4(0.f, 0.f, 0.f, 0.f);
        uint32_t Bh = sb + ABUF, Bl = Bh + BBUF;
#pragma unroll
        for (int i = 0; i < 3; i++) {
            int idx = tid + i * 256, n = idx >> 2, c = idx & 3;
            uint32_t off = (uint32_t)(n * A_ST + c * 16);
            CP_ASYNC16(Bh + off, (const char*)(g_whi + n * FIN + c * 8));
            CP_ASYNC16(Bl + off, (const char*)(g_wlo + n * FIN + c * 8));
        }
        CP_COMMIT();
    }

    for (int kc = 0; kc < 8; kc++) {
        int b = kc & 1;
        uint32_t Ah = sb + b * BUFSZ;
        uint32_t Al = Ah + 64 * A_ST;
        uint32_t Bh = Ah + ABUF;
        uint32_t Bl = Bh + BBUF;

        // ---- STS A (hi/lo split) ----
#pragma unroll
        for (int i = 0; i < 2; i++) {
            int r = (i == 0) ? ar0 : ar1;
            int c4 = (i == 0) ? ac0 : ac1;
            float4 a = aReg[i];
            uint32_t h01 = pack_hi(a.x, a.y), h23 = pack_hi(a.z, a.w);
            uint32_t l01 = pack_lo(a.x, a.y), l23 = pack_lo(a.z, a.w);
            uint32_t off = (uint32_t)(r * A_ST + c4 * 8);
            asm volatile("st.shared.v2.u32 [%0], {%1,%2};" :: "r"(Ah + off), "r"(h01), "r"(h23) : "memory");
            asm volatile("st.shared.v2.u32 [%0], {%1,%2};" :: "r"(Al + off), "r"(l01), "r"(l23) : "memory");
        }
        CP_WAIT0();
        __syncthreads();

        // ---- prefetch next chunk (overlaps mma) ----
        if (kc < 7) {
            int k0 = (kc + 1) * 32;
            int g0 = rowBlock + ar0, g1 = rowBlock + ar1;
            aReg[0] = (g0 < N_NODES) ? *((const float4*)(x + (size_t)g0 * FIN + k0) + ac0)
                                     : make_float4(0.f, 0.f, 0.f, 0.f);
            aReg[1] = (g1 < N_NODES) ? *((const float4*)(x + (size_t)g1 * FIN + k0) + ac1)
                                     : make_float4(0.f, 0.f, 0.f, 0.f);
            uint32_t nBh = sb + (b ^ 1) * BUFSZ + ABUF;
            uint32_t nBl = nBh + BBUF;
#pragma unroll
            for (int i = 0; i < 3; i++) {
                int idx = tid + i * 256, n = idx >> 2, c = idx & 3;
                uint32_t off = (uint32_t)(n * A_ST + c * 16);
                CP_ASYNC16(nBh + off, (const char*)(g_whi + n * FIN + k0 + c * 8));
                CP_ASYNC16(nBl + off, (const char*)(g_wlo + n * FIN + k0 + c * 8));
            }
            CP_COMMIT();
        }

        // ---- mma over two k16 sub-chunks ----
        int lrow = lane & 15;
        int kcol = (lane >> 4) * 16;
#pragma unroll
        for (int sk = 0; sk < 2; sk++) {
            uint32_t koff = (uint32_t)(sk * 32 + kcol);
            uint32_t ah[2][4], al[2][4];
#pragma unroll
            for (int mf = 0; mf < 2; mf++) {
                uint32_t addr = Ah + (uint32_t)((warp_m + mf * 16 + lrow) * A_ST) + koff;
                ldsm_x4(ah[mf], addr);
                ldsm_x4(al[mf], addr + 64 * A_ST);
            }
            uint32_t bh[3][4], bl[3][4];
#pragma unroll
            for (int j = 0; j < 3; j++) {
                uint32_t addr = Bh + (uint32_t)((warp_n + j * 16 + lrow) * A_ST) + koff;
                ldsm_x4(bh[j], addr);
                ldsm_x4(bl[j], addr + BBUF);
            }
#pragma unroll
            for (int mf = 0; mf < 2; mf++)
#pragma unroll
                for (int nf = 0; nf < 6; nf++) {
                    int j = nf >> 1, hf = nf & 1;
                    mma_bf16(acc[mf][nf], ah[mf], bh[j][hf], bh[j][2 + hf]);
                    mma_bf16(acc[mf][nf], ah[mf], bl[j][hf], bl[j][2 + hf]);
                    mma_bf16(acc[mf][nf], al[mf], bh[j][hf], bh[j][2 + hf]);
                }
        }
    }

    // ---- epilogue ----
    int g  = lane >> 2;
    int tg = lane & 3;
#pragma unroll
    for (int mf = 0; mf < 2; mf++) {
        int r0 = rowBlock + warp_m + mf * 16 + g;
        int r1 = r0 + 8;
#pragma unroll
        for (int nf = 0; nf < 6; nf++) {
            int ng = warp_n + nf * 8 + tg * 2;
            int v = ng >> 6;
            int col = ng & 63;
            float* base = g_xw + (size_t)v * N_NODES * NHID + col;
            if (r0 < N_NODES)
                *(float2*)(base + (size_t)r0 * NHID) = make_float2(acc[mf][nf][0], acc[mf][nf][1]);
            if (r1 < N_NODES)
                *(float2*)(base + (size_t)r1 * NHID) = make_float2(acc[mf][nf][2], acc[mf][nf][3]);
        }
    }
}

// ---------------- gather1 ----------------
__global__ void k_gather1(float* __restrict__ out,
                          const float* __restrict__ b1a, const float* __restrict__ b1b,
                          const float* __restrict__ b1c,
                          const float* __restrict__ W2a, const float* __restrict__ W2b,
                          const float* __restrict__ W2c,
                          const float* __restrict__ b2a, const float* __restrict__ b2b,
                          const float* __restrict__ b2c) {
    int gtid = blockIdx.x * blockDim.x + threadIdx.x;
    int node = gtid >> 5;
    int lane = gtid & 31;
    if (node >= N_NODES) return;

    float2 fsum = make_float2(0.f, 0.f);
    float selfsum = 0.f;
#pragma unroll
    for (int v = 0; v < 3; v++) {
        const float* b1 = (v == 0) ? b1a : (v == 1) ? b1b : b1c;
        const float* W2 = (v == 0) ? W2a : (v == 1) ? W2b : W2c;
        int nv = v * N_NODES + node;
        const float2* xwv = (const float2*)g_xw + (size_t)v * N_NODES * 32;

        float d1 = g_dinv[2 * nv + 0];
        float d2 = g_dinv[2 * nv + 1];
        float2 self = xwv[(size_t)node * 32 + lane];
        float sc = d1 * d1;
        float2 acc = make_float2(self.x * sc, self.y * sc);

        int base = g_off[nv];
        int cnt  = g_degI[nv];
        for (int e = 0; e < cnt; e++) {
            int4 p = g_ed[base + e];
            float c = __int_as_float(p.y);
            float2 m = xwv[(size_t)p.x * 32 + lane];
            acc.x = fmaf(m.x, c, acc.x);
            acc.y = fmaf(m.y, c, acc.y);
        }

        float h0 = fmaxf(acc.x + b1[lane * 2 + 0], 0.f);
        float h1 = fmaxf(acc.y + b1[lane * 2 + 1], 0.f);
        fsum.x += h0;
        fsum.y += h1;
        float p = h0 * W2[lane * 2 + 0] + h1 * W2[lane * 2 + 1];
#pragma unroll
        for (int o = 16; o > 0; o >>= 1) p += __shfl_xor_sync(0xffffffffu, p, o);
        if (lane == 0) g_hw[nv] = p;
        selfsum = fmaf(p, d2 * d2, selfsum);
    }
    *(float2*)(out + N_NODES + (size_t)node * NHID + lane * 2) = fsum;
    if (lane == 0) out[node] = selfsum + b2a[0] + b2b[0] + b2c[0];
}

// ---------------- gather2 ----------------
__global__ void k_gather2(float* __restrict__ out) {
    int gtid = blockIdx.x * blockDim.x + threadIdx.x;
    int node = gtid >> 5;
    int lane = gtid & 31;
    if (node >= N_NODES) return;

    float add = 0.f;
#pragma unroll
    for (int v = 0; v < 3; v++) {
        int nv = v * N_NODES + node;
        int base = g_off[nv];
        int cnt  = g_degI[nv];
        const float* hwv = g_hw + v * N_NODES;
        for (int e = lane; e < cnt; e += 32) {
            int4 p = g_ed[base + e];
            add = fmaf(hwv[p.x], __int_as_float(p.z), add);
        }
    }
#pragma unroll
    for (int o = 16; o > 0; o >>= 1) add += __shfl_xor_sync(0xffffffffu, add, o);
    if (lane == 0) out[node] += add;
}

// ---------------- launch ----------------
extern "C" void kernel_launch(void* const* d_in, const int* in_sizes, int n_in,
                              void* d_out, int out_size) {
    const float* x   = (const float*)d_in[0];
    const int*   ei0 = (const int*)d_in[1];
    const int*   ei1 = (const int*)d_in[2];
    const int*   ei2 = (const int*)d_in[3];
    const float* w0  = (const float*)d_in[4];
    const float* w1  = (const float*)d_in[5];
    const float* w2  = (const float*)d_in[6];
    const float* W1a = (const float*)d_in[7];
    const float* b1a = (const float*)d_in[8];
    const float* W2a = (const float*)d_in[9];
    const float* b2a = (const float*)d_in[10];
    const float* W1b = (const float*)d_in[11];
    const float* b1b = (const float*)d_in[12];
    const float* W2b = (const float*)d_in[13];
    const float* b2b = (const float*)d_in[14];
    const float* W1c = (const float*)d_in[15];
    const float* b1c = (const float*)d_in[16];
    const float* W2c = (const float*)d_in[17];
    const float* b2c = (const float*)d_in[18];
    float* out = (float*)d_out;

    static int smem_set = 0;
    if (!smem_set) {
        cudaFuncSetAttribute(k_gemm_mma, cudaFuncAttributeMaxDynamicSharedMemorySize, GSMEM);
        smem_set = 1;
    }

    // launch #4 gets profiled by ncu -> keep the GEMM there
    k_zero<<<NBLK, 256>>>();                                                   // 1
    k_prepW<<<(192 * FIN + 255) / 256, 256>>>(W1a, W1b, W1c);                  // 2
    k_deg<<<dim3((N_EDGES + 255) / 256, 3), 256>>>(ei0, ei1, ei2, w0, w1, w2); // 3
    k_gemm_mma<<<(N_NODES + 63) / 64, 256, GSMEM>>>(x);                        // 4 <- profiled
    k_scan1<<<NBLK, 256>>>();                                                  // 5
    k_scan2<<<1, 1024>>>();                                                    // 6
    k_scan3<<<NBLK, 256>>>();                                                  // 7
    k_fill<<<dim3((N_EDGES + 255) / 256, 3), 256>>>(ei0, ei1, ei2, w0, w1, w2);// 8
    k_gather1<<<(N_NODES * 32 + 255) / 256, 256>>>(out, b1a, b1b, b1c,
                                                   W2a, W2b, W2c, b2a, b2b, b2c); // 9
    k_gather2<<<(N_NODES * 32 + 255) / 256, 256>>>(out);                       // 10
}